// round 1
// baseline (speedup 1.0000x reference)
#include <cuda_runtime.h>
#include <cuda_bf16.h>
#include <math.h>

// Problem shape (fixed by the reference).
#define Bq      4
#define SEQ     2048
#define DMODEL  1024
#define NH      16
#define DH      64
#define ROWS    (Bq * SEQ)      // 8192

static __device__ __constant__ float kEPS = 1.1920929e-07f;   // fp32 finfo eps

// Scratch: device globals (no cudaMalloc allowed). 4 x 32MB.
__device__ float g_Q[ROWS * DMODEL];
__device__ float g_K[ROWS * DMODEL];
__device__ float g_V[ROWS * DMODEL];
__device__ float g_O[ROWS * DMODEL];

// ---------------------------------------------------------------------------
// GEMM (NT): C[M,N] = A[M,K] * B[N,K]^T.  All row-major, K contiguous.
// 128x128 tile, BK=16, 256 threads, 8x8 per-thread microtile.
// ---------------------------------------------------------------------------
__global__ void __launch_bounds__(256)
gemm_nt_128(const float* __restrict__ A, const float* __restrict__ B,
            float* __restrict__ C, int M, int N, int K)
{
    __shared__ float As[16][128];
    __shared__ float Bs[16][128];

    const int tid = threadIdx.x;
    const int bm  = blockIdx.y * 128;
    const int bn  = blockIdx.x * 128;
    const int lr  = tid >> 2;          // 0..63   (load row)
    const int lc  = (tid & 3) << 2;    // 0,4,8,12 (load col4)
    const int tx  = tid & 15;
    const int ty  = tid >> 4;

    float acc[8][8];
#pragma unroll
    for (int i = 0; i < 8; i++)
#pragma unroll
        for (int j = 0; j < 8; j++) acc[i][j] = 0.f;

    for (int k0 = 0; k0 < K; k0 += 16) {
#pragma unroll
        for (int i = 0; i < 2; i++) {
            int row = lr + i * 64;
            float4 va = *(const float4*)(A + (size_t)(bm + row) * K + k0 + lc);
            As[lc + 0][row] = va.x; As[lc + 1][row] = va.y;
            As[lc + 2][row] = va.z; As[lc + 3][row] = va.w;
            float4 vb = *(const float4*)(B + (size_t)(bn + row) * K + k0 + lc);
            Bs[lc + 0][row] = vb.x; Bs[lc + 1][row] = vb.y;
            Bs[lc + 2][row] = vb.z; Bs[lc + 3][row] = vb.w;
        }
        __syncthreads();

#pragma unroll
        for (int kk = 0; kk < 16; kk++) {
            float a[8], b[8];
            *(float4*)(a)     = *(const float4*)(&As[kk][ty * 8]);
            *(float4*)(a + 4) = *(const float4*)(&As[kk][ty * 8 + 4]);
            *(float4*)(b)     = *(const float4*)(&Bs[kk][tx * 8]);
            *(float4*)(b + 4) = *(const float4*)(&Bs[kk][tx * 8 + 4]);
#pragma unroll
            for (int i = 0; i < 8; i++)
#pragma unroll
                for (int j = 0; j < 8; j++)
                    acc[i][j] = fmaf(a[i], b[j], acc[i][j]);
        }
        __syncthreads();
    }

#pragma unroll
    for (int i = 0; i < 8; i++) {
        float4 v0 = make_float4(acc[i][0], acc[i][1], acc[i][2], acc[i][3]);
        float4 v1 = make_float4(acc[i][4], acc[i][5], acc[i][6], acc[i][7]);
        float* cp = C + (size_t)(bm + ty * 8 + i) * N + bn + tx * 8;
        *(float4*)(cp)     = v0;
        *(float4*)(cp + 4) = v1;
    }
}

// ---------------------------------------------------------------------------
// Per-head RMS norm over the last DH=64 elements of each (row, head) chunk.
// Layout is (ROWS, DMODEL) => ROWS*NH contiguous 64-float chunks.
// One warp per chunk.
// ---------------------------------------------------------------------------
__global__ void __launch_bounds__(256)
rmsnorm_kernel(float* __restrict__ X, const float* __restrict__ w, int nchunks)
{
    int warp = (blockIdx.x * blockDim.x + threadIdx.x) >> 5;
    int lane = threadIdx.x & 31;
    if (warp >= nchunks) return;

    float* p = X + (size_t)warp * DH;
    float a = p[lane];
    float b = p[lane + 32];
    float ss = a * a + b * b;
#pragma unroll
    for (int o = 16; o > 0; o >>= 1)
        ss += __shfl_xor_sync(0xFFFFFFFFu, ss, o);
    float r = rsqrtf(ss * (1.0f / (float)DH) + kEPS);
    p[lane]      = a * r * w[lane];
    p[lane + 32] = b * r * w[lane + 32];
}

// ---------------------------------------------------------------------------
// Flash attention, fp32. One thread owns one query row (q[64], o[64] in regs).
// K/V tiles of 16x64 staged in SMEM; all threads read the same key vector
// (broadcast => conflict-free LDS.128). Online softmax per tile of 16 keys.
// Grid: (SEQ/128, Bq*NH), 128 threads.
// ---------------------------------------------------------------------------
__global__ void __launch_bounds__(128)
flash_attn(const float* __restrict__ Q, const float* __restrict__ K,
           const float* __restrict__ V, float* __restrict__ O)
{
    const int TK = 16;
    __shared__ float Ks[TK][DH];
    __shared__ float Vs[TK][DH];

    const int bh = blockIdx.y;       // b*NH + h
    const int b  = bh >> 4;
    const int h  = bh & 15;
    const int t  = threadIdx.x;
    const size_t rowbase = (size_t)b * SEQ;
    const int qrow = blockIdx.x * 128 + t;

    const float* qp = Q + (rowbase + qrow) * DMODEL + h * DH;
    float q[DH];
#pragma unroll
    for (int i = 0; i < DH; i += 4)
        *(float4*)(q + i) = *(const float4*)(qp + i);

    float o[DH];
#pragma unroll
    for (int i = 0; i < DH; i++) o[i] = 0.f;

    float mmax = -INFINITY;
    float l = 0.f;
    const float scale = 0.125f;   // 1/sqrt(64)

    for (int kt = 0; kt < SEQ; kt += TK) {
        __syncthreads();
        // stage K/V tile: TK*64 floats = 256 float4, 2 per thread
#pragma unroll
        for (int i = 0; i < 2; i++) {
            int f4  = t + i * 128;          // 0..255
            int row = f4 >> 4;              // 0..15
            int c4  = (f4 & 15) << 2;       // 0..60
            const size_t g = (rowbase + kt + row) * (size_t)DMODEL + h * DH + c4;
            *(float4*)(&Ks[row][c4]) = *(const float4*)(K + g);
            *(float4*)(&Vs[row][c4]) = *(const float4*)(V + g);
        }
        __syncthreads();

        float s[TK];
#pragma unroll
        for (int j = 0; j < TK; j++) {
            float acc = 0.f;
#pragma unroll
            for (int d = 0; d < DH; d += 4) {
                float4 kv = *(const float4*)(&Ks[j][d]);
                acc = fmaf(q[d],     kv.x, acc);
                acc = fmaf(q[d + 1], kv.y, acc);
                acc = fmaf(q[d + 2], kv.z, acc);
                acc = fmaf(q[d + 3], kv.w, acc);
            }
            s[j] = acc * scale;
        }

        float tmax = s[0];
#pragma unroll
        for (int j = 1; j < TK; j++) tmax = fmaxf(tmax, s[j]);
        float mnew = fmaxf(mmax, tmax);
        float corr = __expf(mmax - mnew);   // first iter: exp(-inf)=0
        l *= corr;
#pragma unroll
        for (int d = 0; d < DH; d++) o[d] *= corr;

#pragma unroll
        for (int j = 0; j < TK; j++) {
            float p = __expf(s[j] - mnew);
            l += p;
#pragma unroll
            for (int d = 0; d < DH; d += 4) {
                float4 vv = *(const float4*)(&Vs[j][d]);
                o[d]     = fmaf(p, vv.x, o[d]);
                o[d + 1] = fmaf(p, vv.y, o[d + 1]);
                o[d + 2] = fmaf(p, vv.z, o[d + 2]);
                o[d + 3] = fmaf(p, vv.w, o[d + 3]);
            }
        }
        mmax = mnew;
    }

    const float inv = 1.f / l;
    float* op = O + (rowbase + qrow) * DMODEL + h * DH;
#pragma unroll
    for (int d = 0; d < DH; d += 4) {
        float4 r;
        r.x = o[d] * inv; r.y = o[d + 1] * inv;
        r.z = o[d + 2] * inv; r.w = o[d + 3] * inv;
        *(float4*)(op + d) = r;
    }
}

// ---------------------------------------------------------------------------
// Launch: Q/K/V projections -> RMS norm -> flash attention -> output proj.
// All plain kernel launches on the capture stream; no allocs, no syncs.
// ---------------------------------------------------------------------------
extern "C" void kernel_launch(void* const* d_in, const int* in_sizes, int n_in,
                              void* d_out, int out_size)
{
    const float* x  = (const float*)d_in[0];
    const float* Wq = (const float*)d_in[1];
    const float* Wk = (const float*)d_in[2];
    const float* Wv = (const float*)d_in[3];
    const float* Wo = (const float*)d_in[4];
    const float* qn = (const float*)d_in[5];
    const float* kn = (const float*)d_in[6];
    float* out = (float*)d_out;

    float *Qp, *Kp, *Vp, *Op;
    cudaGetSymbolAddress((void**)&Qp, g_Q);
    cudaGetSymbolAddress((void**)&Kp, g_K);
    cudaGetSymbolAddress((void**)&Vp, g_V);
    cudaGetSymbolAddress((void**)&Op, g_O);

    dim3 ggrid(DMODEL / 128, ROWS / 128);   // (8, 64)

    gemm_nt_128<<<ggrid, 256>>>(x, Wq, Qp, ROWS, DMODEL, DMODEL);
    gemm_nt_128<<<ggrid, 256>>>(x, Wk, Kp, ROWS, DMODEL, DMODEL);
    gemm_nt_128<<<ggrid, 256>>>(x, Wv, Vp, ROWS, DMODEL, DMODEL);

    const int nchunks = ROWS * NH;                    // 131072
    const int nblocks = nchunks / (256 / 32);         // 16384
    rmsnorm_kernel<<<nblocks, 256>>>(Qp, qn, nchunks);
    rmsnorm_kernel<<<nblocks, 256>>>(Kp, kn, nchunks);

    flash_attn<<<dim3(SEQ / 128, Bq * NH), 128>>>(Qp, Kp, Vp, Op);

    gemm_nt_128<<<ggrid, 256>>>(Op, Wo, out, ROWS, DMODEL, DMODEL);
}

// round 3
// speedup vs baseline: 1.3221x; 1.3221x over previous
#include <cuda_runtime.h>
#include <cuda_bf16.h>
#include <math.h>
#include <cstdint>

// Problem shape (fixed by the reference).
#define Bq      4
#define SEQ     2048
#define DMODEL  1024
#define NH      16
#define DH      64
#define ROWS    (Bq * SEQ)      // 8192

#define F32_EPS 1.1920929e-07f

// Scratch: device globals (no cudaMalloc allowed). 4 x 32MB.
__device__ float g_Q[ROWS * DMODEL];
__device__ float g_K[ROWS * DMODEL];
__device__ float g_V[ROWS * DMODEL];
__device__ float g_O[ROWS * DMODEL];

// ===========================================================================
// Helpers: tf32 mma.sync (sm_80+ PTX -> works on plain sm_103 target),
// cp.async 16B, smem address conversion.
// ===========================================================================
__device__ __forceinline__ uint32_t smem_to_u32(const void* p) {
    uint32_t a;
    asm("{ .reg .u64 t; cvta.to.shared.u64 t, %1; cvt.u32.u64 %0, t; }"
        : "=r"(a) : "l"(p));
    return a;
}
__device__ __forceinline__ uint32_t f2tf32(float f) {
    uint32_t r;
    asm("cvt.rna.tf32.f32 %0, %1;" : "=r"(r) : "f"(f));
    return r;
}
__device__ __forceinline__ void mma_tf32(float* c, const uint32_t* a,
                                         const uint32_t* b) {
    asm volatile(
        "mma.sync.aligned.m16n8k8.row.col.f32.tf32.tf32.f32 "
        "{%0,%1,%2,%3}, {%4,%5,%6,%7}, {%8,%9}, {%0,%1,%2,%3};"
        : "+f"(c[0]), "+f"(c[1]), "+f"(c[2]), "+f"(c[3])
        : "r"(a[0]), "r"(a[1]), "r"(a[2]), "r"(a[3]), "r"(b[0]), "r"(b[1]));
}
__device__ __forceinline__ void cp_async16(uint32_t dst, const void* src) {
    asm volatile("cp.async.ca.shared.global [%0], [%1], 16;"
                 :: "r"(dst), "l"(src));
}
#define CP_COMMIT() asm volatile("cp.async.commit_group;" ::: "memory")
#define CP_WAIT(n)  asm volatile("cp.async.wait_group %0;" :: "n"(n) : "memory")

// ===========================================================================
// tf32 tensor-core GEMM (NT): C[M,N] = A[M,K] * B[N,K]^T, fp32 in/out.
// CTA tile 128x128, BK=32, 256 threads (8 warps in 4(M) x 2(N)).
// Warp tile 32x64 = 2 m-frags x 8 n-frags of m16n8k8.
// cp.async double-buffered SMEM, stride 36 floats => conflict-free frags.
// do_rms: fuse per-head (64-col) RMS norm (weight w) into the epilogue.
// ===========================================================================
#define BK      32
#define NCHUNK  (DMODEL / BK)     // 32
#define ASTR    36                // smem row stride in floats
#define TILEF   (128 * ASTR)      // floats per tile buffer (4608)
#define SM_BYTES (4 * TILEF * 4)  // A[2] + B[2] = 73728 bytes

__global__ void __launch_bounds__(256)
gemm_mma_tf32(const float* __restrict__ A, const float* __restrict__ B,
              float* __restrict__ C, const float* __restrict__ w, int do_rms)
{
    extern __shared__ float smem[];
    // layout: As[0], As[1], Bs[0], Bs[1], each TILEF floats
    const uint32_t sb = smem_to_u32(smem);
    const int tid  = threadIdx.x;
    const int wid  = tid >> 5;
    const int lane = tid & 31;
    const int g    = lane >> 2;      // group id 0..7
    const int t    = lane & 3;       // thread-in-group 0..3
    const int warpM = wid >> 1;      // 0..3
    const int warpN = wid & 1;       // 0..1
    const int bm = blockIdx.y * 128;
    const int bn = blockIdx.x * 128;

    const float* Ag = A + (size_t)bm * DMODEL;
    const float* Bg = B + (size_t)bn * DMODEL;

    // per-thread load slots: 4 float4 for A, 4 for B per chunk
    const int lrow = tid >> 2;            // base row pattern not used; use idx scheme
    (void)lrow;

    float acc[2][8][4];
#pragma unroll
    for (int i = 0; i < 2; i++)
#pragma unroll
        for (int j = 0; j < 8; j++)
#pragma unroll
            for (int k = 0; k < 4; k++) acc[i][j][k] = 0.f;

    auto load_chunk = [&](int chunk, int buf) {
        const uint32_t abase = sb + (uint32_t)(buf * TILEF) * 4u;
        const uint32_t bbase = sb + (uint32_t)((2 + buf) * TILEF) * 4u;
        const size_t kofs = (size_t)chunk * BK;
#pragma unroll
        for (int it = 0; it < 4; it++) {
            const int idx = tid + it * 256;      // 0..1023
            const int row = idx >> 3;            // 0..127
            const int c4  = idx & 7;             // float4 within row
            const uint32_t so = (uint32_t)(row * ASTR + c4 * 4) * 4u;
            cp_async16(abase + so, Ag + (size_t)row * DMODEL + kofs + c4 * 4);
            cp_async16(bbase + so, Bg + (size_t)row * DMODEL + kofs + c4 * 4);
        }
    };

    load_chunk(0, 0);
    CP_COMMIT();

    for (int i = 0; i < NCHUNK; i++) {
        const int buf = i & 1;
        if (i + 1 < NCHUNK) {
            load_chunk(i + 1, buf ^ 1);
            CP_COMMIT();
            CP_WAIT(1);
        } else {
            CP_WAIT(0);
        }
        __syncthreads();

        const float* As = smem + buf * TILEF;
        const float* Bs = smem + (2 + buf) * TILEF;
        const int arow = warpM * 32 + g;
        const int brow = warpN * 64 + g;

#pragma unroll
        for (int ks = 0; ks < 4; ks++) {
            const int k0 = ks * 8;
            uint32_t a[2][4];
#pragma unroll
            for (int mf = 0; mf < 2; mf++) {
                const float* ap = As + (arow + mf * 16) * ASTR + k0 + t;
                a[mf][0] = f2tf32(ap[0]);
                a[mf][1] = f2tf32(ap[8 * ASTR]);
                a[mf][2] = f2tf32(ap[4]);
                a[mf][3] = f2tf32(ap[8 * ASTR + 4]);
            }
            uint32_t b[8][2];
#pragma unroll
            for (int nf = 0; nf < 8; nf++) {
                const float* bp = Bs + (brow + nf * 8) * ASTR + k0 + t;
                b[nf][0] = f2tf32(bp[0]);
                b[nf][1] = f2tf32(bp[4]);
            }
#pragma unroll
            for (int mf = 0; mf < 2; mf++)
#pragma unroll
                for (int nf = 0; nf < 8; nf++)
                    mma_tf32(acc[mf][nf], a[mf], b[nf]);
        }
        __syncthreads();
    }

    // ---------------- epilogue (optionally fused per-head RMS norm) --------
#pragma unroll
    for (int mf = 0; mf < 2; mf++) {
        if (do_rms) {
            float ssl = 0.f, ssh = 0.f;
#pragma unroll
            for (int nf = 0; nf < 8; nf++) {
                ssl += acc[mf][nf][0] * acc[mf][nf][0]
                     + acc[mf][nf][1] * acc[mf][nf][1];
                ssh += acc[mf][nf][2] * acc[mf][nf][2]
                     + acc[mf][nf][3] * acc[mf][nf][3];
            }
            // reduce across the 4 threads sharing these rows (lane bits 0,1)
            ssl += __shfl_xor_sync(0xFFFFFFFFu, ssl, 1);
            ssl += __shfl_xor_sync(0xFFFFFFFFu, ssl, 2);
            ssh += __shfl_xor_sync(0xFFFFFFFFu, ssh, 1);
            ssh += __shfl_xor_sync(0xFFFFFFFFu, ssh, 2);
            const float rl = rsqrtf(ssl * (1.0f / 64.0f) + F32_EPS);
            const float rh = rsqrtf(ssh * (1.0f / 64.0f) + F32_EPS);
#pragma unroll
            for (int nf = 0; nf < 8; nf++) {
                const int hc = nf * 8 + 2 * t;    // col within head (0..63)
                const float w0 = w[hc], w1 = w[hc + 1];
                acc[mf][nf][0] *= rl * w0;
                acc[mf][nf][1] *= rl * w1;
                acc[mf][nf][2] *= rh * w0;
                acc[mf][nf][3] *= rh * w1;
            }
        }
        const int rlo = bm + warpM * 32 + mf * 16 + g;
        float* c0 = C + (size_t)rlo * DMODEL + bn + warpN * 64 + 2 * t;
        float* c1 = c0 + 8 * DMODEL;
#pragma unroll
        for (int nf = 0; nf < 8; nf++) {
            *(float2*)(c0 + nf * 8) = make_float2(acc[mf][nf][0], acc[mf][nf][1]);
            *(float2*)(c1 + nf * 8) = make_float2(acc[mf][nf][2], acc[mf][nf][3]);
        }
    }
}

// ---------------------------------------------------------------------------
// Flash attention, fp32 SIMT (unchanged; Round-4 target).
// ---------------------------------------------------------------------------
__global__ void __launch_bounds__(128)
flash_attn(const float* __restrict__ Q, const float* __restrict__ K,
           const float* __restrict__ V, float* __restrict__ O)
{
    const int TK = 16;
    __shared__ float Ks[TK][DH];
    __shared__ float Vs[TK][DH];

    const int bh = blockIdx.y;
    const int b  = bh >> 4;
    const int h  = bh & 15;
    const int t  = threadIdx.x;
    const size_t rowbase = (size_t)b * SEQ;
    const int qrow = blockIdx.x * 128 + t;

    const float* qp = Q + (rowbase + qrow) * DMODEL + h * DH;
    float q[DH];
#pragma unroll
    for (int i = 0; i < DH; i += 4)
        *(float4*)(q + i) = *(const float4*)(qp + i);

    float o[DH];
#pragma unroll
    for (int i = 0; i < DH; i++) o[i] = 0.f;

    float mmax = -INFINITY;
    float l = 0.f;
    const float scale = 0.125f;

    for (int kt = 0; kt < SEQ; kt += TK) {
        __syncthreads();
#pragma unroll
        for (int i = 0; i < 2; i++) {
            int f4  = t + i * 128;
            int row = f4 >> 4;
            int c4  = (f4 & 15) << 2;
            const size_t gg = (rowbase + kt + row) * (size_t)DMODEL + h * DH + c4;
            *(float4*)(&Ks[row][c4]) = *(const float4*)(K + gg);
            *(float4*)(&Vs[row][c4]) = *(const float4*)(V + gg);
        }
        __syncthreads();

        float s[TK];
#pragma unroll
        for (int j = 0; j < TK; j++) {
            float acc = 0.f;
#pragma unroll
            for (int d = 0; d < DH; d += 4) {
                float4 kv = *(const float4*)(&Ks[j][d]);
                acc = fmaf(q[d],     kv.x, acc);
                acc = fmaf(q[d + 1], kv.y, acc);
                acc = fmaf(q[d + 2], kv.z, acc);
                acc = fmaf(q[d + 3], kv.w, acc);
            }
            s[j] = acc * scale;
        }

        float tmax = s[0];
#pragma unroll
        for (int j = 1; j < TK; j++) tmax = fmaxf(tmax, s[j]);
        float mnew = fmaxf(mmax, tmax);
        float corr = __expf(mmax - mnew);
        l *= corr;
#pragma unroll
        for (int d = 0; d < DH; d++) o[d] *= corr;

#pragma unroll
        for (int j = 0; j < TK; j++) {
            float p = __expf(s[j] - mnew);
            l += p;
#pragma unroll
            for (int d = 0; d < DH; d += 4) {
                float4 vv = *(const float4*)(&Vs[j][d]);
                o[d]     = fmaf(p, vv.x, o[d]);
                o[d + 1] = fmaf(p, vv.y, o[d + 1]);
                o[d + 2] = fmaf(p, vv.z, o[d + 2]);
                o[d + 3] = fmaf(p, vv.w, o[d + 3]);
            }
        }
        mmax = mnew;
    }

    const float inv = 1.f / l;
    float* op = O + (rowbase + qrow) * DMODEL + h * DH;
#pragma unroll
    for (int d = 0; d < DH; d += 4) {
        float4 r;
        r.x = o[d] * inv; r.y = o[d + 1] * inv;
        r.z = o[d + 2] * inv; r.w = o[d + 3] * inv;
        *(float4*)(op + d) = r;
    }
}

// ---------------------------------------------------------------------------
// Launch: mma.sync Q/K/V projections (RMS fused into Q/K) -> flash attention
// -> mma.sync output projection.
// ---------------------------------------------------------------------------
extern "C" void kernel_launch(void* const* d_in, const int* in_sizes, int n_in,
                              void* d_out, int out_size)
{
    const float* x  = (const float*)d_in[0];
    const float* Wq = (const float*)d_in[1];
    const float* Wk = (const float*)d_in[2];
    const float* Wv = (const float*)d_in[3];
    const float* Wo = (const float*)d_in[4];
    const float* qn = (const float*)d_in[5];
    const float* kn = (const float*)d_in[6];
    float* out = (float*)d_out;

    float *Qp, *Kp, *Vp, *Op;
    cudaGetSymbolAddress((void**)&Qp, g_Q);
    cudaGetSymbolAddress((void**)&Kp, g_K);
    cudaGetSymbolAddress((void**)&Vp, g_V);
    cudaGetSymbolAddress((void**)&Op, g_O);

    cudaFuncSetAttribute(gemm_mma_tf32,
                         cudaFuncAttributeMaxDynamicSharedMemorySize, SM_BYTES);

    dim3 ggrid(DMODEL / 128, ROWS / 128);   // (8, 64)

    gemm_mma_tf32<<<ggrid, 256, SM_BYTES>>>(x, Wq, Qp, qn, 1);
    gemm_mma_tf32<<<ggrid, 256, SM_BYTES>>>(x, Wk, Kp, kn, 1);
    gemm_mma_tf32<<<ggrid, 256, SM_BYTES>>>(x, Wv, Vp, nullptr, 0);

    flash_attn<<<dim3(SEQ / 128, Bq * NH), 128>>>(Qp, Kp, Vp, Op);

    gemm_mma_tf32<<<ggrid, 256, SM_BYTES>>>(Op, Wo, out, nullptr, 0);
}

// round 4
// speedup vs baseline: 4.7246x; 3.5736x over previous
#include <cuda_runtime.h>
#include <cuda_bf16.h>
#include <math.h>
#include <cstdint>

// Problem shape (fixed by the reference).
#define Bq      4
#define SEQ     2048
#define DMODEL  1024
#define NH      16
#define DH      64
#define ROWS    (Bq * SEQ)      // 8192

#define F32_EPS 1.1920929e-07f

// Scratch: device globals (no cudaMalloc allowed). 4 x 32MB.
__device__ float g_Q[ROWS * DMODEL];
__device__ float g_K[ROWS * DMODEL];
__device__ float g_V[ROWS * DMODEL];
__device__ float g_O[ROWS * DMODEL];

// ===========================================================================
// Helpers: tf32 mma.sync, cp.async 16B, smem address conversion.
// ===========================================================================
__device__ __forceinline__ uint32_t smem_to_u32(const void* p) {
    uint32_t a;
    asm("{ .reg .u64 t; cvta.to.shared.u64 t, %1; cvt.u32.u64 %0, t; }"
        : "=r"(a) : "l"(p));
    return a;
}
__device__ __forceinline__ uint32_t f2tf32(float f) {
    uint32_t r;
    asm("cvt.rna.tf32.f32 %0, %1;" : "=r"(r) : "f"(f));
    return r;
}
__device__ __forceinline__ void mma_tf32(float* c, const uint32_t* a,
                                         const uint32_t* b) {
    asm volatile(
        "mma.sync.aligned.m16n8k8.row.col.f32.tf32.tf32.f32 "
        "{%0,%1,%2,%3}, {%4,%5,%6,%7}, {%8,%9}, {%0,%1,%2,%3};"
        : "+f"(c[0]), "+f"(c[1]), "+f"(c[2]), "+f"(c[3])
        : "r"(a[0]), "r"(a[1]), "r"(a[2]), "r"(a[3]), "r"(b[0]), "r"(b[1]));
}
__device__ __forceinline__ void cp_async16(uint32_t dst, const void* src) {
    asm volatile("cp.async.ca.shared.global [%0], [%1], 16;"
                 :: "r"(dst), "l"(src));
}
#define CP_COMMIT() asm volatile("cp.async.commit_group;" ::: "memory")
#define CP_WAIT(n)  asm volatile("cp.async.wait_group %0;" :: "n"(n) : "memory")

// ===========================================================================
// tf32 tensor-core GEMM (NT): C[M,N] = A[M,K] * B[N,K]^T (unchanged from R3).
// ===========================================================================
#define BK      32
#define NCHUNK  (DMODEL / BK)     // 32
#define ASTR    36
#define TILEF   (128 * ASTR)
#define SM_BYTES (4 * TILEF * 4)  // 73728 bytes

__global__ void __launch_bounds__(256)
gemm_mma_tf32(const float* __restrict__ A, const float* __restrict__ B,
              float* __restrict__ C, const float* __restrict__ w, int do_rms)
{
    extern __shared__ float smem[];
    const uint32_t sb = smem_to_u32(smem);
    const int tid  = threadIdx.x;
    const int wid  = tid >> 5;
    const int lane = tid & 31;
    const int g    = lane >> 2;
    const int t    = lane & 3;
    const int warpM = wid >> 1;
    const int warpN = wid & 1;
    const int bm = blockIdx.y * 128;
    const int bn = blockIdx.x * 128;

    const float* Ag = A + (size_t)bm * DMODEL;
    const float* Bg = B + (size_t)bn * DMODEL;

    float acc[2][8][4];
#pragma unroll
    for (int i = 0; i < 2; i++)
#pragma unroll
        for (int j = 0; j < 8; j++)
#pragma unroll
            for (int k = 0; k < 4; k++) acc[i][j][k] = 0.f;

    auto load_chunk = [&](int chunk, int buf) {
        const uint32_t abase = sb + (uint32_t)(buf * TILEF) * 4u;
        const uint32_t bbase = sb + (uint32_t)((2 + buf) * TILEF) * 4u;
        const size_t kofs = (size_t)chunk * BK;
#pragma unroll
        for (int it = 0; it < 4; it++) {
            const int idx = tid + it * 256;
            const int row = idx >> 3;
            const int c4  = idx & 7;
            const uint32_t so = (uint32_t)(row * ASTR + c4 * 4) * 4u;
            cp_async16(abase + so, Ag + (size_t)row * DMODEL + kofs + c4 * 4);
            cp_async16(bbase + so, Bg + (size_t)row * DMODEL + kofs + c4 * 4);
        }
    };

    load_chunk(0, 0);
    CP_COMMIT();

    for (int i = 0; i < NCHUNK; i++) {
        const int buf = i & 1;
        if (i + 1 < NCHUNK) {
            load_chunk(i + 1, buf ^ 1);
            CP_COMMIT();
            CP_WAIT(1);
        } else {
            CP_WAIT(0);
        }
        __syncthreads();

        const float* As = smem + buf * TILEF;
        const float* Bs = smem + (2 + buf) * TILEF;
        const int arow = warpM * 32 + g;
        const int brow = warpN * 64 + g;

#pragma unroll
        for (int ks = 0; ks < 4; ks++) {
            const int k0 = ks * 8;
            uint32_t a[2][4];
#pragma unroll
            for (int mf = 0; mf < 2; mf++) {
                const float* ap = As + (arow + mf * 16) * ASTR + k0 + t;
                a[mf][0] = f2tf32(ap[0]);
                a[mf][1] = f2tf32(ap[8 * ASTR]);
                a[mf][2] = f2tf32(ap[4]);
                a[mf][3] = f2tf32(ap[8 * ASTR + 4]);
            }
            uint32_t b[8][2];
#pragma unroll
            for (int nf = 0; nf < 8; nf++) {
                const float* bp = Bs + (brow + nf * 8) * ASTR + k0 + t;
                b[nf][0] = f2tf32(bp[0]);
                b[nf][1] = f2tf32(bp[4]);
            }
#pragma unroll
            for (int mf = 0; mf < 2; mf++)
#pragma unroll
                for (int nf = 0; nf < 8; nf++)
                    mma_tf32(acc[mf][nf], a[mf], b[nf]);
        }
        __syncthreads();
    }

#pragma unroll
    for (int mf = 0; mf < 2; mf++) {
        if (do_rms) {
            float ssl = 0.f, ssh = 0.f;
#pragma unroll
            for (int nf = 0; nf < 8; nf++) {
                ssl += acc[mf][nf][0] * acc[mf][nf][0]
                     + acc[mf][nf][1] * acc[mf][nf][1];
                ssh += acc[mf][nf][2] * acc[mf][nf][2]
                     + acc[mf][nf][3] * acc[mf][nf][3];
            }
            ssl += __shfl_xor_sync(0xFFFFFFFFu, ssl, 1);
            ssl += __shfl_xor_sync(0xFFFFFFFFu, ssl, 2);
            ssh += __shfl_xor_sync(0xFFFFFFFFu, ssh, 1);
            ssh += __shfl_xor_sync(0xFFFFFFFFu, ssh, 2);
            const float rl = rsqrtf(ssl * (1.0f / 64.0f) + F32_EPS);
            const float rh = rsqrtf(ssh * (1.0f / 64.0f) + F32_EPS);
#pragma unroll
            for (int nf = 0; nf < 8; nf++) {
                const int hc = nf * 8 + 2 * t;
                const float w0 = w[hc], w1 = w[hc + 1];
                acc[mf][nf][0] *= rl * w0;
                acc[mf][nf][1] *= rl * w1;
                acc[mf][nf][2] *= rh * w0;
                acc[mf][nf][3] *= rh * w1;
            }
        }
        const int rlo = bm + warpM * 32 + mf * 16 + g;
        float* c0 = C + (size_t)rlo * DMODEL + bn + warpN * 64 + 2 * t;
        float* c1 = c0 + 8 * DMODEL;
#pragma unroll
        for (int nf = 0; nf < 8; nf++) {
            *(float2*)(c0 + nf * 8) = make_float2(acc[mf][nf][0], acc[mf][nf][1]);
            *(float2*)(c1 + nf * 8) = make_float2(acc[mf][nf][2], acc[mf][nf][3]);
        }
    }
}

// ===========================================================================
// Flash attention with tf32 mma.sync.
// CTA: 128 q-rows of one (b,h). 4 warps, each 32 q-rows (2 m16 frags).
// KV tiles of 64 keys, cp.async double-buffered.
// S=Q*K^T via MMA (Q frags resident in regs, scale folded into Q).
// Online softmax in C-frag registers; P -> per-warp SMEM -> A-frags for P*V.
// ===========================================================================
#define KSTR 68
#define VSTR 72
#define PSTR 68
#define FA_KS0  0
#define FA_KS1  (64 * KSTR)                   // 4352
#define FA_VS0  (2 * 64 * KSTR)               // 8704
#define FA_VS1  (FA_VS0 + 64 * VSTR)          // 13312
#define FA_PS   (FA_VS0 + 2 * 64 * VSTR)      // 17920
#define FA_FLOATS (FA_PS + 128 * PSTR)        // 26624
#define FA_BYTES (FA_FLOATS * 4)              // 106496

__global__ void __launch_bounds__(128)
flash_attn_mma(const float* __restrict__ Q, const float* __restrict__ K,
               const float* __restrict__ V, float* __restrict__ O)
{
    extern __shared__ float smem[];
    const uint32_t sb = smem_to_u32(smem);
    const int tid  = threadIdx.x;
    const int wid  = tid >> 5;
    const int lane = tid & 31;
    const int g    = lane >> 2;
    const int t    = lane & 3;
    const int bh = blockIdx.y;
    const int b  = bh >> 4;
    const int h  = bh & 15;
    const size_t rowbase = (size_t)b * SEQ;
    const int qm0 = blockIdx.x * 128;
    const int m0  = wid * 32;

    // ---- stage Q tile (128 x 64) into PS, then extract A-frags ----
    {
        const float* Qg = Q + (rowbase + qm0) * DMODEL + h * DH;
#pragma unroll
        for (int i = 0; i < 16; i++) {
            const int idx = tid + i * 128;
            const int row = idx >> 4;
            const int c4  = idx & 15;
            cp_async16(sb + (uint32_t)(FA_PS + row * PSTR + c4 * 4) * 4u,
                       Qg + (size_t)row * DMODEL + c4 * 4);
        }
        CP_COMMIT(); CP_WAIT(0);
        __syncthreads();
    }

    uint32_t qf[2][8][4];
#pragma unroll
    for (int mf = 0; mf < 2; mf++)
#pragma unroll
        for (int ks = 0; ks < 8; ks++) {
            const float* qp = smem + FA_PS + (m0 + mf * 16 + g) * PSTR + ks * 8 + t;
            qf[mf][ks][0] = f2tf32(qp[0] * 0.125f);
            qf[mf][ks][1] = f2tf32(qp[8 * PSTR] * 0.125f);
            qf[mf][ks][2] = f2tf32(qp[4] * 0.125f);
            qf[mf][ks][3] = f2tf32(qp[8 * PSTR + 4] * 0.125f);
        }

    float acc_o[2][8][4];
#pragma unroll
    for (int i = 0; i < 2; i++)
#pragma unroll
        for (int j = 0; j < 8; j++)
#pragma unroll
            for (int k = 0; k < 4; k++) acc_o[i][j][k] = 0.f;
    float mrow[2][2] = {{-INFINITY, -INFINITY}, {-INFINITY, -INFINITY}};
    float lrow[2][2] = {{0.f, 0.f}, {0.f, 0.f}};

    auto load_kv = [&](int tile, int buf) {
        const float* Kg = K + (rowbase + tile * 64) * DMODEL + h * DH;
        const float* Vg = V + (rowbase + tile * 64) * DMODEL + h * DH;
        const uint32_t kb = sb + (uint32_t)(buf ? FA_KS1 : FA_KS0) * 4u;
        const uint32_t vb = sb + (uint32_t)(buf ? FA_VS1 : FA_VS0) * 4u;
#pragma unroll
        for (int i = 0; i < 8; i++) {
            const int idx = tid + i * 128;
            const int row = idx >> 4;
            const int c4  = idx & 15;
            cp_async16(kb + (uint32_t)(row * KSTR + c4 * 4) * 4u,
                       Kg + (size_t)row * DMODEL + c4 * 4);
            cp_async16(vb + (uint32_t)(row * VSTR + c4 * 4) * 4u,
                       Vg + (size_t)row * DMODEL + c4 * 4);
        }
    };

    load_kv(0, 0);
    CP_COMMIT();

    const int NT = SEQ / 64;   // 32
    for (int it = 0; it < NT; it++) {
        const int buf = it & 1;
        __syncthreads();                 // prev iter done with buf^1 / PS safe
        if (it + 1 < NT) {
            load_kv(it + 1, buf ^ 1);
            CP_COMMIT();
            CP_WAIT(1);
        } else {
            CP_WAIT(0);
        }
        __syncthreads();

        // ---- S = Q * K^T ----
        float s[2][8][4];
#pragma unroll
        for (int i = 0; i < 2; i++)
#pragma unroll
            for (int j = 0; j < 8; j++)
#pragma unroll
                for (int k = 0; k < 4; k++) s[i][j][k] = 0.f;

        const float* Kb = smem + (buf ? FA_KS1 : FA_KS0);
#pragma unroll
        for (int ks = 0; ks < 8; ks++) {
            uint32_t bf[8][2];
#pragma unroll
            for (int nf = 0; nf < 8; nf++) {
                const float* kp = Kb + (nf * 8 + g) * KSTR + ks * 8 + t;
                bf[nf][0] = f2tf32(kp[0]);
                bf[nf][1] = f2tf32(kp[4]);
            }
#pragma unroll
            for (int mf = 0; mf < 2; mf++)
#pragma unroll
                for (int nf = 0; nf < 8; nf++)
                    mma_tf32(s[mf][nf], qf[mf][ks], bf[nf]);
        }

        // ---- online softmax; write P to SMEM ----
#pragma unroll
        for (int mf = 0; mf < 2; mf++) {
            float tm0 = -INFINITY, tm1 = -INFINITY;
#pragma unroll
            for (int nf = 0; nf < 8; nf++) {
                tm0 = fmaxf(tm0, fmaxf(s[mf][nf][0], s[mf][nf][1]));
                tm1 = fmaxf(tm1, fmaxf(s[mf][nf][2], s[mf][nf][3]));
            }
            tm0 = fmaxf(tm0, __shfl_xor_sync(0xFFFFFFFFu, tm0, 1));
            tm0 = fmaxf(tm0, __shfl_xor_sync(0xFFFFFFFFu, tm0, 2));
            tm1 = fmaxf(tm1, __shfl_xor_sync(0xFFFFFFFFu, tm1, 1));
            tm1 = fmaxf(tm1, __shfl_xor_sync(0xFFFFFFFFu, tm1, 2));

            const float mn0 = fmaxf(mrow[mf][0], tm0);
            const float mn1 = fmaxf(mrow[mf][1], tm1);
            const float corr0 = __expf(mrow[mf][0] - mn0);
            const float corr1 = __expf(mrow[mf][1] - mn1);
            mrow[mf][0] = mn0; mrow[mf][1] = mn1;

            float rs0 = 0.f, rs1 = 0.f;
            float* p0 = smem + FA_PS + (m0 + mf * 16 + g) * PSTR + 2 * t;
            float* p1 = p0 + 8 * PSTR;
#pragma unroll
            for (int nf = 0; nf < 8; nf++) {
                const float e00 = __expf(s[mf][nf][0] - mn0);
                const float e01 = __expf(s[mf][nf][1] - mn0);
                const float e10 = __expf(s[mf][nf][2] - mn1);
                const float e11 = __expf(s[mf][nf][3] - mn1);
                rs0 += e00 + e01;
                rs1 += e10 + e11;
                *(float2*)(p0 + nf * 8) = make_float2(e00, e01);
                *(float2*)(p1 + nf * 8) = make_float2(e10, e11);
            }
            rs0 += __shfl_xor_sync(0xFFFFFFFFu, rs0, 1);
            rs0 += __shfl_xor_sync(0xFFFFFFFFu, rs0, 2);
            rs1 += __shfl_xor_sync(0xFFFFFFFFu, rs1, 1);
            rs1 += __shfl_xor_sync(0xFFFFFFFFu, rs1, 2);
            lrow[mf][0] = lrow[mf][0] * corr0 + rs0;
            lrow[mf][1] = lrow[mf][1] * corr1 + rs1;
#pragma unroll
            for (int nf = 0; nf < 8; nf++) {
                acc_o[mf][nf][0] *= corr0;
                acc_o[mf][nf][1] *= corr0;
                acc_o[mf][nf][2] *= corr1;
                acc_o[mf][nf][3] *= corr1;
            }
        }
        __syncwarp();

        // ---- O += P * V ----
        const float* Vb = smem + (buf ? FA_VS1 : FA_VS0);
#pragma unroll
        for (int ks = 0; ks < 8; ks++) {
            uint32_t bf[8][2];
#pragma unroll
            for (int nf = 0; nf < 8; nf++) {
                const float* vp = Vb + (ks * 8 + t) * VSTR + nf * 8 + g;
                bf[nf][0] = f2tf32(vp[0]);
                bf[nf][1] = f2tf32(vp[4 * VSTR]);
            }
#pragma unroll
            for (int mf = 0; mf < 2; mf++) {
                uint32_t af[4];
                const float* pp = smem + FA_PS + (m0 + mf * 16 + g) * PSTR + ks * 8 + t;
                af[0] = f2tf32(pp[0]);
                af[1] = f2tf32(pp[8 * PSTR]);
                af[2] = f2tf32(pp[4]);
                af[3] = f2tf32(pp[8 * PSTR + 4]);
#pragma unroll
                for (int nf = 0; nf < 8; nf++)
                    mma_tf32(acc_o[mf][nf], af, bf[nf]);
            }
        }
    }

    // ---- epilogue: O / l -> global ----
#pragma unroll
    for (int mf = 0; mf < 2; mf++) {
        const float inv0 = 1.f / lrow[mf][0];
        const float inv1 = 1.f / lrow[mf][1];
        float* op0 = O + (rowbase + qm0 + m0 + mf * 16 + g) * (size_t)DMODEL
                       + h * DH + 2 * t;
        float* op1 = op0 + 8 * DMODEL;
#pragma unroll
        for (int nf = 0; nf < 8; nf++) {
            *(float2*)(op0 + nf * 8) =
                make_float2(acc_o[mf][nf][0] * inv0, acc_o[mf][nf][1] * inv0);
            *(float2*)(op1 + nf * 8) =
                make_float2(acc_o[mf][nf][2] * inv1, acc_o[mf][nf][3] * inv1);
        }
    }
}

// ---------------------------------------------------------------------------
// Launch.
// ---------------------------------------------------------------------------
extern "C" void kernel_launch(void* const* d_in, const int* in_sizes, int n_in,
                              void* d_out, int out_size)
{
    const float* x  = (const float*)d_in[0];
    const float* Wq = (const float*)d_in[1];
    const float* Wk = (const float*)d_in[2];
    const float* Wv = (const float*)d_in[3];
    const float* Wo = (const float*)d_in[4];
    const float* qn = (const float*)d_in[5];
    const float* kn = (const float*)d_in[6];
    float* out = (float*)d_out;

    float *Qp, *Kp, *Vp, *Op;
    cudaGetSymbolAddress((void**)&Qp, g_Q);
    cudaGetSymbolAddress((void**)&Kp, g_K);
    cudaGetSymbolAddress((void**)&Vp, g_V);
    cudaGetSymbolAddress((void**)&Op, g_O);

    cudaFuncSetAttribute(gemm_mma_tf32,
                         cudaFuncAttributeMaxDynamicSharedMemorySize, SM_BYTES);
    cudaFuncSetAttribute(flash_attn_mma,
                         cudaFuncAttributeMaxDynamicSharedMemorySize, FA_BYTES);

    dim3 ggrid(DMODEL / 128, ROWS / 128);   // (8, 64)

    gemm_mma_tf32<<<ggrid, 256, SM_BYTES>>>(x, Wq, Qp, qn, 1);
    gemm_mma_tf32<<<ggrid, 256, SM_BYTES>>>(x, Wk, Kp, kn, 1);
    gemm_mma_tf32<<<ggrid, 256, SM_BYTES>>>(x, Wv, Vp, nullptr, 0);

    flash_attn_mma<<<dim3(SEQ / 128, Bq * NH), 128, FA_BYTES>>>(Qp, Kp, Vp, Op);

    gemm_mma_tf32<<<ggrid, 256, SM_BYTES>>>(Op, Wo, out, nullptr, 0);
}

// round 5
// speedup vs baseline: 10.1401x; 2.1462x over previous
#include <cuda_runtime.h>
#include <cuda_fp16.h>
#include <math.h>
#include <cstdint>

// Problem shape (fixed by the reference).
#define Bq      4
#define SEQ     2048
#define DMODEL  1024
#define NH      16
#define DH      64
#define ROWS    (Bq * SEQ)      // 8192

#define F32_EPS 1.1920929e-07f

// fp16 scratch: device globals (no cudaMalloc allowed).
__device__ __half g_xh[ROWS * DMODEL];
__device__ __half g_Wqh[DMODEL * DMODEL];
__device__ __half g_Wkh[DMODEL * DMODEL];
__device__ __half g_Wvh[DMODEL * DMODEL];
__device__ __half g_Woh[DMODEL * DMODEL];
__device__ __half g_Qh[ROWS * DMODEL];
__device__ __half g_Kh[ROWS * DMODEL];
__device__ __half g_Vh[ROWS * DMODEL];
__device__ __half g_Oh[ROWS * DMODEL];

// ===========================================================================
// Helpers.
// ===========================================================================
__device__ __forceinline__ uint32_t smem_to_u32(const void* p) {
    uint32_t a;
    asm("{ .reg .u64 t; cvta.to.shared.u64 t, %1; cvt.u32.u64 %0, t; }"
        : "=r"(a) : "l"(p));
    return a;
}
__device__ __forceinline__ void mma_f16(float* c, uint32_t a0, uint32_t a1,
                                        uint32_t a2, uint32_t a3,
                                        uint32_t b0, uint32_t b1) {
    asm volatile(
        "mma.sync.aligned.m16n8k16.row.col.f32.f16.f16.f32 "
        "{%0,%1,%2,%3}, {%4,%5,%6,%7}, {%8,%9}, {%0,%1,%2,%3};"
        : "+f"(c[0]), "+f"(c[1]), "+f"(c[2]), "+f"(c[3])
        : "r"(a0), "r"(a1), "r"(a2), "r"(a3), "r"(b0), "r"(b1));
}
__device__ __forceinline__ void ldsm_x4(uint32_t& r0, uint32_t& r1,
                                        uint32_t& r2, uint32_t& r3, uint32_t a) {
    asm volatile("ldmatrix.sync.aligned.m8n8.x4.shared.b16 {%0,%1,%2,%3}, [%4];"
                 : "=r"(r0), "=r"(r1), "=r"(r2), "=r"(r3) : "r"(a));
}
__device__ __forceinline__ void ldsm_x4_t(uint32_t& r0, uint32_t& r1,
                                          uint32_t& r2, uint32_t& r3, uint32_t a) {
    asm volatile("ldmatrix.sync.aligned.m8n8.x4.trans.shared.b16 {%0,%1,%2,%3}, [%4];"
                 : "=r"(r0), "=r"(r1), "=r"(r2), "=r"(r3) : "r"(a));
}
__device__ __forceinline__ void cp_async16(uint32_t dst, const void* src) {
    asm volatile("cp.async.cg.shared.global [%0], [%1], 16;"
                 :: "r"(dst), "l"(src));
}
#define CP_COMMIT() asm volatile("cp.async.commit_group;" ::: "memory")
#define CP_WAIT(n)  asm volatile("cp.async.wait_group %0;" :: "n"(n) : "memory")

__device__ __forceinline__ uint32_t packh2(float x, float y) {
    __half2 h = __floats2half2_rn(x, y);
    return *(uint32_t*)&h;
}

// ===========================================================================
// fp32 -> fp16 conversion (x and weights).
// ===========================================================================
__global__ void cvt32to16(const float4* __restrict__ s, uint2* __restrict__ d,
                          int n4) {
    int i = blockIdx.x * blockDim.x + threadIdx.x;
    if (i < n4) {
        float4 v = s[i];
        d[i] = make_uint2(packh2(v.x, v.y), packh2(v.z, v.w));
    }
}

// ===========================================================================
// fp16 tensor-core GEMM (NT): C[M,N] = A[M,K] * B[N,K]^T, fp32 accum.
// CTA 128x128, BK=32, 3-stage cp.async pipeline, 256 threads (8 warps 4x2),
// warp tile 32x64 = 2 mf x 8 nf of m16n8k16. ldmatrix fragment loads.
// do_rms: fused per-head (64-col) RMS norm. out_half: fp16 vs fp32 output.
// ===========================================================================
#define GBK     32
#define GNCH    (DMODEL / GBK)       // 32
#define GASTR   40                   // halves per smem row (80 B)
#define GSTGB   20480                // bytes per stage (A 10240 + B 10240)
#define GSM_BYTES (3 * GSTGB)        // 61440

__global__ void __launch_bounds__(256)
gemm_f16(const __half* __restrict__ A, const __half* __restrict__ B,
         void* __restrict__ Cv, const float* __restrict__ w,
         int do_rms, int out_half)
{
    extern __shared__ __half gsm[];
    const uint32_t sb = smem_to_u32(gsm);
    const int tid  = threadIdx.x;
    const int wid  = tid >> 5;
    const int lane = tid & 31;
    const int g    = lane >> 2;
    const int t    = lane & 3;
    const int warpM = wid >> 1;
    const int warpN = wid & 1;
    const int bm = blockIdx.y * 128;
    const int bn = blockIdx.x * 128;

    const int l15 = lane & 15, lq = lane >> 4;
    const int rbl = lq * 8 + (lane & 7);
    const int cob = ((lane >> 3) & 1) * 8;

    const __half* Ag = A + (size_t)bm * DMODEL;
    const __half* Bg = B + (size_t)bn * DMODEL;

    float acc[2][8][4];
#pragma unroll
    for (int i = 0; i < 2; i++)
#pragma unroll
        for (int j = 0; j < 8; j++)
#pragma unroll
            for (int k = 0; k < 4; k++) acc[i][j][k] = 0.f;

    auto load_stage = [&](int chunk, int st) {
        const uint32_t abase = sb + (uint32_t)st * GSTGB;
        const uint32_t bbase = abase + 10240;
#pragma unroll
        for (int i = 0; i < 2; i++) {
            const int idx = tid + i * 256;     // 0..511
            const int row = idx >> 2;          // 0..127
            const int c8  = idx & 3;           // 8-half chunk
            const uint32_t so = (uint32_t)(row * GASTR + c8 * 8) * 2u;
            const size_t go = (size_t)row * DMODEL + chunk * GBK + c8 * 8;
            cp_async16(abase + so, Ag + go);
            cp_async16(bbase + so, Bg + go);
        }
    };

    load_stage(0, 0); CP_COMMIT();
    load_stage(1, 1); CP_COMMIT();

    for (int i = 0; i < GNCH; i++) {
        const int st = i % 3;
        if (i == GNCH - 1) { CP_WAIT(0); } else { CP_WAIT(1); }
        __syncthreads();
        if (i + 2 < GNCH) { load_stage(i + 2, (i + 2) % 3); CP_COMMIT(); }

        const uint32_t abase = sb + (uint32_t)st * GSTGB;
        const uint32_t bbase = abase + 10240;
#pragma unroll
        for (int ks = 0; ks < 2; ks++) {
            uint32_t a[2][4];
#pragma unroll
            for (int mf = 0; mf < 2; mf++)
                ldsm_x4(a[mf][0], a[mf][1], a[mf][2], a[mf][3],
                        abase + (uint32_t)((warpM * 32 + mf * 16 + l15) * GASTR
                                           + ks * 16 + lq * 8) * 2u);
#pragma unroll
            for (int nfp = 0; nfp < 4; nfp++) {
                uint32_t b0, b1, b2, b3;
                ldsm_x4(b0, b1, b2, b3,
                        bbase + (uint32_t)((warpN * 64 + nfp * 16 + rbl) * GASTR
                                           + ks * 16 + cob) * 2u);
#pragma unroll
                for (int mf = 0; mf < 2; mf++) {
                    mma_f16(acc[mf][2 * nfp],     a[mf][0], a[mf][1], a[mf][2], a[mf][3], b0, b1);
                    mma_f16(acc[mf][2 * nfp + 1], a[mf][0], a[mf][1], a[mf][2], a[mf][3], b2, b3);
                }
            }
        }
    }

    // ---------------- epilogue --------------------------------------------
#pragma unroll
    for (int mf = 0; mf < 2; mf++) {
        if (do_rms) {
            float ssl = 0.f, ssh = 0.f;
#pragma unroll
            for (int nf = 0; nf < 8; nf++) {
                ssl += acc[mf][nf][0] * acc[mf][nf][0]
                     + acc[mf][nf][1] * acc[mf][nf][1];
                ssh += acc[mf][nf][2] * acc[mf][nf][2]
                     + acc[mf][nf][3] * acc[mf][nf][3];
            }
            ssl += __shfl_xor_sync(0xFFFFFFFFu, ssl, 1);
            ssl += __shfl_xor_sync(0xFFFFFFFFu, ssl, 2);
            ssh += __shfl_xor_sync(0xFFFFFFFFu, ssh, 1);
            ssh += __shfl_xor_sync(0xFFFFFFFFu, ssh, 2);
            const float rl = rsqrtf(ssl * (1.0f / 64.0f) + F32_EPS);
            const float rh = rsqrtf(ssh * (1.0f / 64.0f) + F32_EPS);
#pragma unroll
            for (int nf = 0; nf < 8; nf++) {
                const int hc = nf * 8 + 2 * t;
                const float w0 = w[hc], w1 = w[hc + 1];
                acc[mf][nf][0] *= rl * w0;
                acc[mf][nf][1] *= rl * w1;
                acc[mf][nf][2] *= rh * w0;
                acc[mf][nf][3] *= rh * w1;
            }
        }
        const int r0 = bm + warpM * 32 + mf * 16 + g;
        const int cc = bn + warpN * 64 + 2 * t;
        if (out_half) {
            __half* C = (__half*)Cv;
            uint32_t* c0 = (uint32_t*)(C + (size_t)r0 * DMODEL + cc);
            uint32_t* c1 = (uint32_t*)(C + (size_t)(r0 + 8) * DMODEL + cc);
#pragma unroll
            for (int nf = 0; nf < 8; nf++) {
                c0[nf * 4] = packh2(acc[mf][nf][0], acc[mf][nf][1]);
                c1[nf * 4] = packh2(acc[mf][nf][2], acc[mf][nf][3]);
            }
        } else {
            float* C = (float*)Cv;
            float* c0 = C + (size_t)r0 * DMODEL + cc;
            float* c1 = C + (size_t)(r0 + 8) * DMODEL + cc;
#pragma unroll
            for (int nf = 0; nf < 8; nf++) {
                *(float2*)(c0 + nf * 8) = make_float2(acc[mf][nf][0], acc[mf][nf][1]);
                *(float2*)(c1 + nf * 8) = make_float2(acc[mf][nf][2], acc[mf][nf][3]);
            }
        }
    }
}

// ===========================================================================
// fp16 flash attention.
// CTA: 128 q-rows of one (b,h); 8 warps x 16 rows. KV tiles 64, double-buffer.
// S via m16n8k16 (Q frags resident, scale folded); P stays in registers
// (C-frag of S == A-frag of PV); V^T frags via ldmatrix.x4.trans.
// ===========================================================================
#define HSTR 72                       // halves per smem row (144 B)
#define FA_TILEH (64 * HSTR)          // 4608 halves per tile
#define FA_NT (SEQ / 64)              // 32

__global__ void __launch_bounds__(256, 2)
flash_attn_f16(const __half* __restrict__ Q, const __half* __restrict__ K,
               const __half* __restrict__ V, __half* __restrict__ O)
{
    __shared__ __half fs[4 * FA_TILEH];     // [K0][K1][V0][V1]; Q staged over K0K1
    const uint32_t sb = smem_to_u32(fs);
    const int tid  = threadIdx.x;
    const int wid  = tid >> 5;
    const int lane = tid & 31;
    const int g    = lane >> 2;
    const int t    = lane & 3;
    const int bh = blockIdx.y;
    const int b  = bh >> 4;
    const int h  = bh & 15;
    const size_t rowbase = (size_t)b * SEQ;
    const int qm0 = blockIdx.x * 128;
    const int m0  = wid * 16;

    const int l15 = lane & 15, lq = lane >> 4;
    const int rbl = lq * 8 + (lane & 7);             // K ldmatrix row pattern
    const int cob = ((lane >> 3) & 1) * 8;           // K col offset
    const int rv  = ((lane >> 3) & 1) * 8 + (lane & 7);  // V trans row pattern
    const int cv  = lq * 8;                          // V trans col offset

    // ---- stage Q (128 x 64 halves) over [K0][K1], extract frags ----
    {
        const __half* Qg = Q + (rowbase + qm0) * DMODEL + h * DH;
#pragma unroll
        for (int i = 0; i < 4; i++) {
            const int idx = tid + i * 256;
            const int row = idx >> 3, c8 = idx & 7;
            cp_async16(sb + (uint32_t)(row * HSTR + c8 * 8) * 2u,
                       Qg + (size_t)row * DMODEL + c8 * 8);
        }
        CP_COMMIT(); CP_WAIT(0);
        __syncthreads();
    }
    uint32_t qf[4][4];
    const __half2 qsc = __float2half2_rn(0.125f);
#pragma unroll
    for (int ks = 0; ks < 4; ks++) {
        ldsm_x4(qf[ks][0], qf[ks][1], qf[ks][2], qf[ks][3],
                sb + (uint32_t)((m0 + l15) * HSTR + ks * 16 + lq * 8) * 2u);
#pragma unroll
        for (int j = 0; j < 4; j++) {
            __half2* hp = (__half2*)&qf[ks][j];
            *hp = __hmul2(*hp, qsc);
        }
    }
    __syncthreads();   // Q staging region about to be reused by K tiles

    float acc_o[8][4];
#pragma unroll
    for (int j = 0; j < 8; j++)
#pragma unroll
        for (int k = 0; k < 4; k++) acc_o[j][k] = 0.f;
    float mr0 = -INFINITY, mr1 = -INFINITY;
    float lr0 = 0.f, lr1 = 0.f;

    auto load_kv = [&](int tile, int buf) {
        const __half* Kg = K + (rowbase + tile * 64) * DMODEL + h * DH;
        const __half* Vg = V + (rowbase + tile * 64) * DMODEL + h * DH;
        const uint32_t kb = sb + (uint32_t)(buf * FA_TILEH) * 2u;
        const uint32_t vb = sb + (uint32_t)((2 + buf) * FA_TILEH) * 2u;
#pragma unroll
        for (int i = 0; i < 2; i++) {
            const int idx = tid + i * 256;
            const int row = idx >> 3, c8 = idx & 7;
            const uint32_t so = (uint32_t)(row * HSTR + c8 * 8) * 2u;
            const size_t go = (size_t)row * DMODEL + c8 * 8;
            cp_async16(kb + so, Kg + go);
            cp_async16(vb + so, Vg + go);
        }
    };

    load_kv(0, 0);
    CP_COMMIT();

    for (int it = 0; it < FA_NT; it++) {
        const int buf = it & 1;
        __syncthreads();                     // prior iter done reading buf^1
        if (it + 1 < FA_NT) {
            load_kv(it + 1, buf ^ 1);
            CP_COMMIT();
            CP_WAIT(1);
        } else {
            CP_WAIT(0);
        }
        __syncthreads();

        // ---- S = Q * K^T ----
        float s[8][4];
#pragma unroll
        for (int j = 0; j < 8; j++)
#pragma unroll
            for (int k = 0; k < 4; k++) s[j][k] = 0.f;

        const uint32_t kbase = sb + (uint32_t)(buf * FA_TILEH) * 2u;
#pragma unroll
        for (int ks = 0; ks < 4; ks++) {
#pragma unroll
            for (int nfp = 0; nfp < 4; nfp++) {
                uint32_t b0, b1, b2, b3;
                ldsm_x4(b0, b1, b2, b3,
                        kbase + (uint32_t)((nfp * 16 + rbl) * HSTR
                                           + ks * 16 + cob) * 2u);
                mma_f16(s[2 * nfp],     qf[ks][0], qf[ks][1], qf[ks][2], qf[ks][3], b0, b1);
                mma_f16(s[2 * nfp + 1], qf[ks][0], qf[ks][1], qf[ks][2], qf[ks][3], b2, b3);
            }
        }

        // ---- online softmax (rows g and g+8), P packed to half2 regs ----
        float tm0 = -INFINITY, tm1 = -INFINITY;
#pragma unroll
        for (int nf = 0; nf < 8; nf++) {
            tm0 = fmaxf(tm0, fmaxf(s[nf][0], s[nf][1]));
            tm1 = fmaxf(tm1, fmaxf(s[nf][2], s[nf][3]));
        }
        tm0 = fmaxf(tm0, __shfl_xor_sync(0xFFFFFFFFu, tm0, 1));
        tm0 = fmaxf(tm0, __shfl_xor_sync(0xFFFFFFFFu, tm0, 2));
        tm1 = fmaxf(tm1, __shfl_xor_sync(0xFFFFFFFFu, tm1, 1));
        tm1 = fmaxf(tm1, __shfl_xor_sync(0xFFFFFFFFu, tm1, 2));

        const float mn0 = fmaxf(mr0, tm0);
        const float mn1 = fmaxf(mr1, tm1);
        const float corr0 = __expf(mr0 - mn0);
        const float corr1 = __expf(mr1 - mn1);
        mr0 = mn0; mr1 = mn1;

        uint32_t ph[8][2];
        float rs0 = 0.f, rs1 = 0.f;
#pragma unroll
        for (int nf = 0; nf < 8; nf++) {
            const float e00 = __expf(s[nf][0] - mn0);
            const float e01 = __expf(s[nf][1] - mn0);
            const float e10 = __expf(s[nf][2] - mn1);
            const float e11 = __expf(s[nf][3] - mn1);
            rs0 += e00 + e01;
            rs1 += e10 + e11;
            ph[nf][0] = packh2(e00, e01);
            ph[nf][1] = packh2(e10, e11);
        }
        rs0 += __shfl_xor_sync(0xFFFFFFFFu, rs0, 1);
        rs0 += __shfl_xor_sync(0xFFFFFFFFu, rs0, 2);
        rs1 += __shfl_xor_sync(0xFFFFFFFFu, rs1, 1);
        rs1 += __shfl_xor_sync(0xFFFFFFFFu, rs1, 2);
        lr0 = lr0 * corr0 + rs0;
        lr1 = lr1 * corr1 + rs1;
#pragma unroll
        for (int nf = 0; nf < 8; nf++) {
            acc_o[nf][0] *= corr0;
            acc_o[nf][1] *= corr0;
            acc_o[nf][2] *= corr1;
            acc_o[nf][3] *= corr1;
        }

        // ---- O += P * V  (A-frags straight from ph registers) ----
        const uint32_t vbase = sb + (uint32_t)((2 + buf) * FA_TILEH) * 2u;
#pragma unroll
        for (int ks = 0; ks < 4; ks++) {
#pragma unroll
            for (int nfp = 0; nfp < 4; nfp++) {
                uint32_t b0, b1, b2, b3;
                ldsm_x4_t(b0, b1, b2, b3,
                          vbase + (uint32_t)((ks * 16 + rv) * HSTR
                                             + nfp * 16 + cv) * 2u);
                mma_f16(acc_o[2 * nfp],     ph[2 * ks][0], ph[2 * ks][1],
                        ph[2 * ks + 1][0], ph[2 * ks + 1][1], b0, b1);
                mma_f16(acc_o[2 * nfp + 1], ph[2 * ks][0], ph[2 * ks][1],
                        ph[2 * ks + 1][0], ph[2 * ks + 1][1], b2, b3);
            }
        }
    }

    // ---- epilogue: O / l -> fp16 global ----
    const float inv0 = 1.f / lr0;
    const float inv1 = 1.f / lr1;
    __half* o0 = O + (rowbase + qm0 + m0 + g) * (size_t)DMODEL + h * DH + 2 * t;
    __half* o1 = o0 + 8 * DMODEL;
#pragma unroll
    for (int nf = 0; nf < 8; nf++) {
        *(uint32_t*)(o0 + nf * 8) = packh2(acc_o[nf][0] * inv0, acc_o[nf][1] * inv0);
        *(uint32_t*)(o1 + nf * 8) = packh2(acc_o[nf][2] * inv1, acc_o[nf][3] * inv1);
    }
}

// ---------------------------------------------------------------------------
// Launch.
// ---------------------------------------------------------------------------
extern "C" void kernel_launch(void* const* d_in, const int* in_sizes, int n_in,
                              void* d_out, int out_size)
{
    const float* x  = (const float*)d_in[0];
    const float* Wq = (const float*)d_in[1];
    const float* Wk = (const float*)d_in[2];
    const float* Wv = (const float*)d_in[3];
    const float* Wo = (const float*)d_in[4];
    const float* qn = (const float*)d_in[5];
    const float* kn = (const float*)d_in[6];
    float* out = (float*)d_out;

    __half *xh, *wqh, *wkh, *wvh, *woh, *Qh, *Kh, *Vh, *Oh;
    cudaGetSymbolAddress((void**)&xh,  g_xh);
    cudaGetSymbolAddress((void**)&wqh, g_Wqh);
    cudaGetSymbolAddress((void**)&wkh, g_Wkh);
    cudaGetSymbolAddress((void**)&wvh, g_Wvh);
    cudaGetSymbolAddress((void**)&woh, g_Woh);
    cudaGetSymbolAddress((void**)&Qh,  g_Qh);
    cudaGetSymbolAddress((void**)&Kh,  g_Kh);
    cudaGetSymbolAddress((void**)&Vh,  g_Vh);
    cudaGetSymbolAddress((void**)&Oh,  g_Oh);

    cudaFuncSetAttribute(gemm_f16,
                         cudaFuncAttributeMaxDynamicSharedMemorySize, GSM_BYTES);

    // fp32 -> fp16 conversions
    const int nx4 = ROWS * DMODEL / 4;          // 2097152
    const int nw4 = DMODEL * DMODEL / 4;        // 262144
    cvt32to16<<<(nx4 + 255) / 256, 256>>>((const float4*)x,  (uint2*)xh,  nx4);
    cvt32to16<<<(nw4 + 255) / 256, 256>>>((const float4*)Wq, (uint2*)wqh, nw4);
    cvt32to16<<<(nw4 + 255) / 256, 256>>>((const float4*)Wk, (uint2*)wkh, nw4);
    cvt32to16<<<(nw4 + 255) / 256, 256>>>((const float4*)Wv, (uint2*)wvh, nw4);
    cvt32to16<<<(nw4 + 255) / 256, 256>>>((const float4*)Wo, (uint2*)woh, nw4);

    dim3 ggrid(DMODEL / 128, ROWS / 128);   // (8, 64)

    gemm_f16<<<ggrid, 256, GSM_BYTES>>>(xh, wqh, Qh, qn, 1, 1);
    gemm_f16<<<ggrid, 256, GSM_BYTES>>>(xh, wkh, Kh, kn, 1, 1);
    gemm_f16<<<ggrid, 256, GSM_BYTES>>>(xh, wvh, Vh, nullptr, 0, 1);

    flash_attn_f16<<<dim3(SEQ / 128, Bq * NH), 256>>>(Qh, Kh, Vh, Oh);

    gemm_f16<<<ggrid, 256, GSM_BYTES>>>(Oh, woh, out, nullptr, 0, 0);
}

// round 6
// speedup vs baseline: 11.7974x; 1.1634x over previous
#include <cuda_runtime.h>
#include <cuda_fp16.h>
#include <math.h>
#include <cstdint>

// Problem shape (fixed by the reference).
#define Bq      4
#define SEQ     2048
#define DMODEL  1024
#define NH      16
#define DH      64
#define ROWS    (Bq * SEQ)      // 8192

#define F32_EPS 1.1920929e-07f

// fp16 scratch: device globals (no cudaMalloc allowed).
__device__ __half g_xh[ROWS * DMODEL];
__device__ __half g_Wqh[DMODEL * DMODEL];
__device__ __half g_Wkh[DMODEL * DMODEL];
__device__ __half g_Wvh[DMODEL * DMODEL];
__device__ __half g_Woh[DMODEL * DMODEL];
__device__ __half g_Qh[ROWS * DMODEL];
__device__ __half g_Kh[ROWS * DMODEL];
__device__ __half g_Vh[ROWS * DMODEL];
__device__ __half g_Oh[ROWS * DMODEL];

// ===========================================================================
// Helpers.
// ===========================================================================
__device__ __forceinline__ uint32_t smem_to_u32(const void* p) {
    uint32_t a;
    asm("{ .reg .u64 t; cvta.to.shared.u64 t, %1; cvt.u32.u64 %0, t; }"
        : "=r"(a) : "l"(p));
    return a;
}
__device__ __forceinline__ float ex2f(float x) {
    float r;
    asm("ex2.approx.f32 %0, %1;" : "=f"(r) : "f"(x));
    return r;
}
__device__ __forceinline__ void mma_f16(float* c, uint32_t a0, uint32_t a1,
                                        uint32_t a2, uint32_t a3,
                                        uint32_t b0, uint32_t b1) {
    asm volatile(
        "mma.sync.aligned.m16n8k16.row.col.f32.f16.f16.f32 "
        "{%0,%1,%2,%3}, {%4,%5,%6,%7}, {%8,%9}, {%0,%1,%2,%3};"
        : "+f"(c[0]), "+f"(c[1]), "+f"(c[2]), "+f"(c[3])
        : "r"(a0), "r"(a1), "r"(a2), "r"(a3), "r"(b0), "r"(b1));
}
__device__ __forceinline__ void ldsm_x4(uint32_t& r0, uint32_t& r1,
                                        uint32_t& r2, uint32_t& r3, uint32_t a) {
    asm volatile("ldmatrix.sync.aligned.m8n8.x4.shared.b16 {%0,%1,%2,%3}, [%4];"
                 : "=r"(r0), "=r"(r1), "=r"(r2), "=r"(r3) : "r"(a));
}
__device__ __forceinline__ void ldsm_x4_t(uint32_t& r0, uint32_t& r1,
                                          uint32_t& r2, uint32_t& r3, uint32_t a) {
    asm volatile("ldmatrix.sync.aligned.m8n8.x4.trans.shared.b16 {%0,%1,%2,%3}, [%4];"
                 : "=r"(r0), "=r"(r1), "=r"(r2), "=r"(r3) : "r"(a));
}
__device__ __forceinline__ void cp_async16(uint32_t dst, const void* src) {
    asm volatile("cp.async.cg.shared.global [%0], [%1], 16;"
                 :: "r"(dst), "l"(src));
}
#define CP_COMMIT() asm volatile("cp.async.commit_group;" ::: "memory")
#define CP_WAIT(n)  asm volatile("cp.async.wait_group %0;" :: "n"(n) : "memory")

__device__ __forceinline__ uint32_t packh2(float x, float y) {
    __half2 h = __floats2half2_rn(x, y);
    return *(uint32_t*)&h;
}

// ===========================================================================
// Fused fp32 -> fp16 conversion: x (2M float4) then 4 weights (256K each).
// ===========================================================================
#define NX4 (ROWS * DMODEL / 4)      // 2097152
#define NW4 (DMODEL * DMODEL / 4)    // 262144

__global__ void cvt_all(const float4* __restrict__ x,
                        const float4* __restrict__ w0,
                        const float4* __restrict__ w1,
                        const float4* __restrict__ w2,
                        const float4* __restrict__ w3,
                        uint2* __restrict__ dx, uint2* __restrict__ dw0,
                        uint2* __restrict__ dw1, uint2* __restrict__ dw2,
                        uint2* __restrict__ dw3)
{
    int i = blockIdx.x * blockDim.x + threadIdx.x;
    const float4* s;
    uint2* d;
    int idx;
    if (i < NX4) {
        s = x; d = dx; idx = i;
    } else {
        int j = i - NX4;
        int wsel = j >> 18;                 // NW4 = 2^18
        idx = j & (NW4 - 1);
        s = wsel == 0 ? w0 : wsel == 1 ? w1 : wsel == 2 ? w2 : w3;
        d = wsel == 0 ? dw0 : wsel == 1 ? dw1 : wsel == 2 ? dw2 : dw3;
    }
    float4 v = s[idx];
    d[idx] = make_uint2(packh2(v.x, v.y), packh2(v.z, v.w));
}

// ===========================================================================
// fp16 tensor-core GEMM body (NT): C[M,N] = A[M,K]*B[N,K]^T, fp32 accum.
// CTA 128x128, BK=32, 3-stage cp.async pipeline, 256 threads (8 warps 4x2).
// ===========================================================================
#define GBK     32
#define GNCH    (DMODEL / GBK)       // 32
#define GASTR   40                   // halves per smem row (80 B)
#define GSTGB   20480                // bytes per stage (A 10240 + B 10240)
#define GSM_BYTES (3 * GSTGB)        // 61440

__device__ __forceinline__ void
gemm_body(__half* gsm, const __half* __restrict__ A, const __half* __restrict__ B,
          void* __restrict__ Cv, const float* __restrict__ w,
          int do_rms, int out_half, int bm, int bn)
{
    const uint32_t sb = smem_to_u32(gsm);
    const int tid  = threadIdx.x;
    const int wid  = tid >> 5;
    const int lane = tid & 31;
    const int g    = lane >> 2;
    const int t    = lane & 3;
    const int warpM = wid >> 1;
    const int warpN = wid & 1;

    const int l15 = lane & 15, lq = lane >> 4;
    const int rbl = lq * 8 + (lane & 7);
    const int cob = ((lane >> 3) & 1) * 8;

    const __half* Ag = A + (size_t)bm * DMODEL;
    const __half* Bg = B + (size_t)bn * DMODEL;

    float acc[2][8][4];
#pragma unroll
    for (int i = 0; i < 2; i++)
#pragma unroll
        for (int j = 0; j < 8; j++)
#pragma unroll
            for (int k = 0; k < 4; k++) acc[i][j][k] = 0.f;

    auto load_stage = [&](int chunk, int st) {
        const uint32_t abase = sb + (uint32_t)st * GSTGB;
        const uint32_t bbase = abase + 10240;
#pragma unroll
        for (int i = 0; i < 2; i++) {
            const int idx = tid + i * 256;
            const int row = idx >> 2;
            const int c8  = idx & 3;
            const uint32_t so = (uint32_t)(row * GASTR + c8 * 8) * 2u;
            const size_t go = (size_t)row * DMODEL + chunk * GBK + c8 * 8;
            cp_async16(abase + so, Ag + go);
            cp_async16(bbase + so, Bg + go);
        }
    };

    load_stage(0, 0); CP_COMMIT();
    load_stage(1, 1); CP_COMMIT();

    for (int i = 0; i < GNCH; i++) {
        const int st = i % 3;
        if (i == GNCH - 1) { CP_WAIT(0); } else { CP_WAIT(1); }
        __syncthreads();
        if (i + 2 < GNCH) { load_stage(i + 2, (i + 2) % 3); CP_COMMIT(); }

        const uint32_t abase = sb + (uint32_t)st * GSTGB;
        const uint32_t bbase = abase + 10240;
#pragma unroll
        for (int ks = 0; ks < 2; ks++) {
            uint32_t a[2][4];
#pragma unroll
            for (int mf = 0; mf < 2; mf++)
                ldsm_x4(a[mf][0], a[mf][1], a[mf][2], a[mf][3],
                        abase + (uint32_t)((warpM * 32 + mf * 16 + l15) * GASTR
                                           + ks * 16 + lq * 8) * 2u);
#pragma unroll
            for (int nfp = 0; nfp < 4; nfp++) {
                uint32_t b0, b1, b2, b3;
                ldsm_x4(b0, b1, b2, b3,
                        bbase + (uint32_t)((warpN * 64 + nfp * 16 + rbl) * GASTR
                                           + ks * 16 + cob) * 2u);
#pragma unroll
                for (int mf = 0; mf < 2; mf++) {
                    mma_f16(acc[mf][2 * nfp],     a[mf][0], a[mf][1], a[mf][2], a[mf][3], b0, b1);
                    mma_f16(acc[mf][2 * nfp + 1], a[mf][0], a[mf][1], a[mf][2], a[mf][3], b2, b3);
                }
            }
        }
    }

    // ---------------- epilogue --------------------------------------------
#pragma unroll
    for (int mf = 0; mf < 2; mf++) {
        if (do_rms) {
            float ssl = 0.f, ssh = 0.f;
#pragma unroll
            for (int nf = 0; nf < 8; nf++) {
                ssl += acc[mf][nf][0] * acc[mf][nf][0]
                     + acc[mf][nf][1] * acc[mf][nf][1];
                ssh += acc[mf][nf][2] * acc[mf][nf][2]
                     + acc[mf][nf][3] * acc[mf][nf][3];
            }
            ssl += __shfl_xor_sync(0xFFFFFFFFu, ssl, 1);
            ssl += __shfl_xor_sync(0xFFFFFFFFu, ssl, 2);
            ssh += __shfl_xor_sync(0xFFFFFFFFu, ssh, 1);
            ssh += __shfl_xor_sync(0xFFFFFFFFu, ssh, 2);
            const float rl = rsqrtf(ssl * (1.0f / 64.0f) + F32_EPS);
            const float rh = rsqrtf(ssh * (1.0f / 64.0f) + F32_EPS);
#pragma unroll
            for (int nf = 0; nf < 8; nf++) {
                const int hc = nf * 8 + 2 * t;
                const float w0 = w[hc], w1 = w[hc + 1];
                acc[mf][nf][0] *= rl * w0;
                acc[mf][nf][1] *= rl * w1;
                acc[mf][nf][2] *= rh * w0;
                acc[mf][nf][3] *= rh * w1;
            }
        }
        const int r0 = bm + warpM * 32 + mf * 16 + g;
        const int cc = bn + warpN * 64 + 2 * t;
        if (out_half) {
            __half* C = (__half*)Cv;
            uint32_t* c0 = (uint32_t*)(C + (size_t)r0 * DMODEL + cc);
            uint32_t* c1 = (uint32_t*)(C + (size_t)(r0 + 8) * DMODEL + cc);
#pragma unroll
            for (int nf = 0; nf < 8; nf++) {
                c0[nf * 4] = packh2(acc[mf][nf][0], acc[mf][nf][1]);
                c1[nf * 4] = packh2(acc[mf][nf][2], acc[mf][nf][3]);
            }
        } else {
            float* C = (float*)Cv;
            float* c0 = C + (size_t)r0 * DMODEL + cc;
            float* c1 = C + (size_t)(r0 + 8) * DMODEL + cc;
#pragma unroll
            for (int nf = 0; nf < 8; nf++) {
                *(float2*)(c0 + nf * 8) = make_float2(acc[mf][nf][0], acc[mf][nf][1]);
                *(float2*)(c1 + nf * 8) = make_float2(acc[mf][nf][2], acc[mf][nf][3]);
            }
        }
    }
}

// Fused QKV projection: grid.x = 24 (matrix = x/8, col tile = x%7), grid.y = 64.
__global__ void __launch_bounds__(256)
gemm_qkv(const __half* __restrict__ A,
         const __half* __restrict__ Bqm, const __half* __restrict__ Bkm,
         const __half* __restrict__ Bvm,
         __half* __restrict__ Cq, __half* __restrict__ Ck, __half* __restrict__ Cv_,
         const float* __restrict__ qn, const float* __restrict__ kn)
{
    extern __shared__ __half gsm[];
    const int m = blockIdx.x >> 3;
    const int bn = (blockIdx.x & 7) * 128;
    const __half* B = m == 0 ? Bqm : m == 1 ? Bkm : Bvm;
    __half* C = m == 0 ? Cq : m == 1 ? Ck : Cv_;
    const float* w = m == 0 ? qn : m == 1 ? kn : nullptr;
    gemm_body(gsm, A, B, C, w, m < 2 ? 1 : 0, 1, blockIdx.y * 128, bn);
}

// Single GEMM (output projection), fp32 out.
__global__ void __launch_bounds__(256)
gemm_f16(const __half* __restrict__ A, const __half* __restrict__ B,
         void* __restrict__ Cv, const float* __restrict__ w,
         int do_rms, int out_half)
{
    extern __shared__ __half gsm[];
    gemm_body(gsm, A, B, Cv, w, do_rms, out_half,
              blockIdx.y * 128, blockIdx.x * 128);
}

// ===========================================================================
// fp16 flash attention — NO online softmax.
// |s| <= 8 (q,k RMS-normed, scale 1/8) => exp(s) <= e^8, l <= 2048 e^8: all
// safely in fp32/fp16 range, so we accumulate unnormalized O and l and divide
// once at the end. log2(e)*0.125 is folded into Q so p = ex2(s) directly.
// CTA: 128 q-rows of one (b,h); 8 warps x 16 rows. KV tiles 64, double-buffer.
// ===========================================================================
#define HSTR 72                       // halves per smem row (144 B)
#define FA_TILEH (64 * HSTR)          // 4608 halves per tile
#define FA_NT (SEQ / 64)              // 32

__global__ void __launch_bounds__(256, 2)
flash_attn_f16(const __half* __restrict__ Q, const __half* __restrict__ K,
               const __half* __restrict__ V, __half* __restrict__ O)
{
    __shared__ __half fs[4 * FA_TILEH];     // [K0][K1][V0][V1]; Q staged over K0K1
    const uint32_t sb = smem_to_u32(fs);
    const int tid  = threadIdx.x;
    const int wid  = tid >> 5;
    const int lane = tid & 31;
    const int g    = lane >> 2;
    const int t    = lane & 3;
    const int bh = blockIdx.y;
    const int b  = bh >> 4;
    const int h  = bh & 15;
    const size_t rowbase = (size_t)b * SEQ;
    const int qm0 = blockIdx.x * 128;
    const int m0  = wid * 16;

    const int l15 = lane & 15, lq = lane >> 4;
    const int rbl = lq * 8 + (lane & 7);             // K ldmatrix row pattern
    const int cob = ((lane >> 3) & 1) * 8;           // K col offset
    const int rv  = ((lane >> 3) & 1) * 8 + (lane & 7);  // V trans row pattern
    const int cv  = lq * 8;                          // V trans col offset

    // ---- stage Q (128 x 64 halves) over [K0][K1], extract frags ----
    {
        const __half* Qg = Q + (rowbase + qm0) * DMODEL + h * DH;
#pragma unroll
        for (int i = 0; i < 4; i++) {
            const int idx = tid + i * 256;
            const int row = idx >> 3, c8 = idx & 7;
            cp_async16(sb + (uint32_t)(row * HSTR + c8 * 8) * 2u,
                       Qg + (size_t)row * DMODEL + c8 * 8);
        }
        CP_COMMIT(); CP_WAIT(0);
        __syncthreads();
    }
    uint32_t qf[4][4];
    // scale = 1/sqrt(64) * log2(e), so ex2(s) == exp(q.k/8)
    const __half2 qsc = __float2half2_rn(0.125f * 1.4426950408889634f);
#pragma unroll
    for (int ks = 0; ks < 4; ks++) {
        ldsm_x4(qf[ks][0], qf[ks][1], qf[ks][2], qf[ks][3],
                sb + (uint32_t)((m0 + l15) * HSTR + ks * 16 + lq * 8) * 2u);
#pragma unroll
        for (int j = 0; j < 4; j++) {
            __half2* hp = (__half2*)&qf[ks][j];
            *hp = __hmul2(*hp, qsc);
        }
    }
    __syncthreads();   // Q staging region about to be reused by K tiles

    float acc_o[8][4];
#pragma unroll
    for (int j = 0; j < 8; j++)
#pragma unroll
        for (int k = 0; k < 4; k++) acc_o[j][k] = 0.f;
    float lr0 = 0.f, lr1 = 0.f;      // per-thread partial row sums

    auto load_kv = [&](int tile, int buf) {
        const __half* Kg = K + (rowbase + tile * 64) * DMODEL + h * DH;
        const __half* Vg = V + (rowbase + tile * 64) * DMODEL + h * DH;
        const uint32_t kb = sb + (uint32_t)(buf * FA_TILEH) * 2u;
        const uint32_t vb = sb + (uint32_t)((2 + buf) * FA_TILEH) * 2u;
#pragma unroll
        for (int i = 0; i < 2; i++) {
            const int idx = tid + i * 256;
            const int row = idx >> 3, c8 = idx & 7;
            const uint32_t so = (uint32_t)(row * HSTR + c8 * 8) * 2u;
            const size_t go = (size_t)row * DMODEL + c8 * 8;
            cp_async16(kb + so, Kg + go);
            cp_async16(vb + so, Vg + go);
        }
    };

    load_kv(0, 0);
    CP_COMMIT();

    for (int it = 0; it < FA_NT; it++) {
        const int buf = it & 1;
        __syncthreads();                     // prior iter done reading buf^1
        if (it + 1 < FA_NT) {
            load_kv(it + 1, buf ^ 1);
            CP_COMMIT();
            CP_WAIT(1);
        } else {
            CP_WAIT(0);
        }
        __syncthreads();

        // ---- S = Q * K^T (in log2 units) ----
        float s[8][4];
#pragma unroll
        for (int j = 0; j < 8; j++)
#pragma unroll
            for (int k = 0; k < 4; k++) s[j][k] = 0.f;

        const uint32_t kbase = sb + (uint32_t)(buf * FA_TILEH) * 2u;
#pragma unroll
        for (int ks = 0; ks < 4; ks++) {
#pragma unroll
            for (int nfp = 0; nfp < 4; nfp++) {
                uint32_t b0, b1, b2, b3;
                ldsm_x4(b0, b1, b2, b3,
                        kbase + (uint32_t)((nfp * 16 + rbl) * HSTR
                                           + ks * 16 + cob) * 2u);
                mma_f16(s[2 * nfp],     qf[ks][0], qf[ks][1], qf[ks][2], qf[ks][3], b0, b1);
                mma_f16(s[2 * nfp + 1], qf[ks][0], qf[ks][1], qf[ks][2], qf[ks][3], b2, b3);
            }
        }

        // ---- p = 2^s; accumulate row sums; pack to fp16 A-frags ----
        uint32_t ph[8][2];
#pragma unroll
        for (int nf = 0; nf < 8; nf++) {
            const float e00 = ex2f(s[nf][0]);
            const float e01 = ex2f(s[nf][1]);
            const float e10 = ex2f(s[nf][2]);
            const float e11 = ex2f(s[nf][3]);
            lr0 += e00 + e01;
            lr1 += e10 + e11;
            ph[nf][0] = packh2(e00, e01);
            ph[nf][1] = packh2(e10, e11);
        }

        // ---- O += P * V ----
        const uint32_t vbase = sb + (uint32_t)((2 + buf) * FA_TILEH) * 2u;
#pragma unroll
        for (int ks = 0; ks < 4; ks++) {
#pragma unroll
            for (int nfp = 0; nfp < 4; nfp++) {
                uint32_t b0, b1, b2, b3;
                ldsm_x4_t(b0, b1, b2, b3,
                          vbase + (uint32_t)((ks * 16 + rv) * HSTR
                                             + nfp * 16 + cv) * 2u);
                mma_f16(acc_o[2 * nfp],     ph[2 * ks][0], ph[2 * ks][1],
                        ph[2 * ks + 1][0], ph[2 * ks + 1][1], b0, b1);
                mma_f16(acc_o[2 * nfp + 1], ph[2 * ks][0], ph[2 * ks][1],
                        ph[2 * ks + 1][0], ph[2 * ks + 1][1], b2, b3);
            }
        }
    }

    // ---- epilogue: reduce l across quad once, O / l -> fp16 global ----
    lr0 += __shfl_xor_sync(0xFFFFFFFFu, lr0, 1);
    lr0 += __shfl_xor_sync(0xFFFFFFFFu, lr0, 2);
    lr1 += __shfl_xor_sync(0xFFFFFFFFu, lr1, 1);
    lr1 += __shfl_xor_sync(0xFFFFFFFFu, lr1, 2);
    const float inv0 = 1.f / lr0;
    const float inv1 = 1.f / lr1;
    __half* o0 = O + (rowbase + qm0 + m0 + g) * (size_t)DMODEL + h * DH + 2 * t;
    __half* o1 = o0 + 8 * DMODEL;
#pragma unroll
    for (int nf = 0; nf < 8; nf++) {
        *(uint32_t*)(o0 + nf * 8) = packh2(acc_o[nf][0] * inv0, acc_o[nf][1] * inv0);
        *(uint32_t*)(o1 + nf * 8) = packh2(acc_o[nf][2] * inv1, acc_o[nf][3] * inv1);
    }
}

// ---------------------------------------------------------------------------
// Launch.
// ---------------------------------------------------------------------------
extern "C" void kernel_launch(void* const* d_in, const int* in_sizes, int n_in,
                              void* d_out, int out_size)
{
    const float* x  = (const float*)d_in[0];
    const float* Wq = (const float*)d_in[1];
    const float* Wk = (const float*)d_in[2];
    const float* Wv = (const float*)d_in[3];
    const float* Wo = (const float*)d_in[4];
    const float* qn = (const float*)d_in[5];
    const float* kn = (const float*)d_in[6];
    float* out = (float*)d_out;

    __half *xh, *wqh, *wkh, *wvh, *woh, *Qh, *Kh, *Vh, *Oh;
    cudaGetSymbolAddress((void**)&xh,  g_xh);
    cudaGetSymbolAddress((void**)&wqh, g_Wqh);
    cudaGetSymbolAddress((void**)&wkh, g_Wkh);
    cudaGetSymbolAddress((void**)&wvh, g_Wvh);
    cudaGetSymbolAddress((void**)&woh, g_Woh);
    cudaGetSymbolAddress((void**)&Qh,  g_Qh);
    cudaGetSymbolAddress((void**)&Kh,  g_Kh);
    cudaGetSymbolAddress((void**)&Vh,  g_Vh);
    cudaGetSymbolAddress((void**)&Oh,  g_Oh);

    cudaFuncSetAttribute(gemm_f16,
                         cudaFuncAttributeMaxDynamicSharedMemorySize, GSM_BYTES);
    cudaFuncSetAttribute(gemm_qkv,
                         cudaFuncAttributeMaxDynamicSharedMemorySize, GSM_BYTES);

    // fused fp32 -> fp16 conversion (x + 4 weights)
    const int ntot = NX4 + 4 * NW4;             // 3145728
    cvt_all<<<ntot / 256, 256>>>((const float4*)x, (const float4*)Wq,
                                 (const float4*)Wk, (const float4*)Wv,
                                 (const float4*)Wo,
                                 (uint2*)xh, (uint2*)wqh, (uint2*)wkh,
                                 (uint2*)wvh, (uint2*)woh);

    // fused QKV projection
    gemm_qkv<<<dim3(24, ROWS / 128), 256, GSM_BYTES>>>(
        xh, wqh, wkh, wvh, Qh, Kh, Vh, qn, kn);

    flash_attn_f16<<<dim3(SEQ / 128, Bq * NH), 256>>>(Qh, Kh, Vh, Oh);

    gemm_f16<<<dim3(DMODEL / 128, ROWS / 128), 256, GSM_BYTES>>>(
        Oh, woh, out, nullptr, 0, 0);
}

// round 7
// speedup vs baseline: 12.4850x; 1.0583x over previous
#include <cuda_runtime.h>
#include <cuda_fp16.h>
#include <math.h>
#include <cstdint>

// Problem shape (fixed by the reference).
#define Bq      4
#define SEQ     2048
#define DMODEL  1024
#define NH      16
#define DH      64
#define ROWS    (Bq * SEQ)      // 8192

#define F32_EPS 1.1920929e-07f

// fp16 scratch: device globals (no cudaMalloc allowed).
__device__ __half g_xh[ROWS * DMODEL];
__device__ __half g_Wqh[DMODEL * DMODEL];
__device__ __half g_Wkh[DMODEL * DMODEL];
__device__ __half g_Wvh[DMODEL * DMODEL];
__device__ __half g_Woh[DMODEL * DMODEL];
__device__ __half g_Qh[ROWS * DMODEL];
__device__ __half g_Kh[ROWS * DMODEL];
__device__ __half g_Vh[ROWS * DMODEL];
__device__ __half g_Oh[ROWS * DMODEL];

// ===========================================================================
// Helpers.
// ===========================================================================
__device__ __forceinline__ uint32_t smem_to_u32(const void* p) {
    uint32_t a;
    asm("{ .reg .u64 t; cvta.to.shared.u64 t, %1; cvt.u32.u64 %0, t; }"
        : "=r"(a) : "l"(p));
    return a;
}
__device__ __forceinline__ void mma_f16(float* c, uint32_t a0, uint32_t a1,
                                        uint32_t a2, uint32_t a3,
                                        uint32_t b0, uint32_t b1) {
    asm volatile(
        "mma.sync.aligned.m16n8k16.row.col.f32.f16.f16.f32 "
        "{%0,%1,%2,%3}, {%4,%5,%6,%7}, {%8,%9}, {%0,%1,%2,%3};"
        : "+f"(c[0]), "+f"(c[1]), "+f"(c[2]), "+f"(c[3])
        : "r"(a0), "r"(a1), "r"(a2), "r"(a3), "r"(b0), "r"(b1));
}
__device__ __forceinline__ void ldsm_x4(uint32_t& r0, uint32_t& r1,
                                        uint32_t& r2, uint32_t& r3, uint32_t a) {
    asm volatile("ldmatrix.sync.aligned.m8n8.x4.shared.b16 {%0,%1,%2,%3}, [%4];"
                 : "=r"(r0), "=r"(r1), "=r"(r2), "=r"(r3) : "r"(a));
}
__device__ __forceinline__ void ldsm_x4_t(uint32_t& r0, uint32_t& r1,
                                          uint32_t& r2, uint32_t& r3, uint32_t a) {
    asm volatile("ldmatrix.sync.aligned.m8n8.x4.trans.shared.b16 {%0,%1,%2,%3}, [%4];"
                 : "=r"(r0), "=r"(r1), "=r"(r2), "=r"(r3) : "r"(a));
}
__device__ __forceinline__ void cp_async16(uint32_t dst, const void* src) {
    asm volatile("cp.async.cg.shared.global [%0], [%1], 16;"
                 :: "r"(dst), "l"(src));
}
#define CP_COMMIT() asm volatile("cp.async.commit_group;" ::: "memory")
#define CP_WAIT(n)  asm volatile("cp.async.wait_group %0;" :: "n"(n) : "memory")

__device__ __forceinline__ uint32_t packh2(float x, float y) {
    __half2 h = __floats2half2_rn(x, y);
    return *(uint32_t*)&h;
}
// 2 exponentials (base 2) on a packed half2 in ONE MUFU op.
__device__ __forceinline__ uint32_t h2ex2(uint32_t x) {
    uint32_t r;
    asm("ex2.approx.f16x2 %0, %1;" : "=r"(r) : "r"(x));
    return r;
}

// ===========================================================================
// Fused fp32 -> fp16 conversion: x (2M float4) then 4 weights (256K each).
// ===========================================================================
#define NX4 (ROWS * DMODEL / 4)      // 2097152
#define NW4 (DMODEL * DMODEL / 4)    // 262144

__global__ void cvt_all(const float4* __restrict__ x,
                        const float4* __restrict__ w0,
                        const float4* __restrict__ w1,
                        const float4* __restrict__ w2,
                        const float4* __restrict__ w3,
                        uint2* __restrict__ dx, uint2* __restrict__ dw0,
                        uint2* __restrict__ dw1, uint2* __restrict__ dw2,
                        uint2* __restrict__ dw3)
{
    int i = blockIdx.x * blockDim.x + threadIdx.x;
    const float4* s;
    uint2* d;
    int idx;
    if (i < NX4) {
        s = x; d = dx; idx = i;
    } else {
        int j = i - NX4;
        int wsel = j >> 18;                 // NW4 = 2^18
        idx = j & (NW4 - 1);
        s = wsel == 0 ? w0 : wsel == 1 ? w1 : wsel == 2 ? w2 : w3;
        d = wsel == 0 ? dw0 : wsel == 1 ? dw1 : wsel == 2 ? dw2 : dw3;
    }
    float4 v = s[idx];
    d[idx] = make_uint2(packh2(v.x, v.y), packh2(v.z, v.w));
}

// ===========================================================================
// fp16 tensor-core GEMM body (NT): C[M,N] = A[M,K]*B[N,K]^T, fp32 accum.
// CTA 128x128, BK=64, 3-stage cp.async pipeline (1 barrier per chunk),
// 256 threads (8 warps 4x2), warp tile 32x64 via m16n8k16 + ldmatrix.
// ===========================================================================
#define GBK     64
#define GNCH    (DMODEL / GBK)       // 16
#define GASTR   72                   // halves per smem row (144 B)
#define GMATB   (128 * GASTR * 2)    // 18432 bytes per matrix per stage
#define GSTGB   (2 * GMATB)          // 36864 bytes per stage
#define GSM_BYTES (3 * GSTGB)        // 110592

__device__ __forceinline__ void
gemm_body(__half* gsm, const __half* __restrict__ A, const __half* __restrict__ B,
          void* __restrict__ Cv, const float* __restrict__ w,
          int do_rms, int out_half, int bm, int bn)
{
    const uint32_t sb = smem_to_u32(gsm);
    const int tid  = threadIdx.x;
    const int wid  = tid >> 5;
    const int lane = tid & 31;
    const int g    = lane >> 2;
    const int t    = lane & 3;
    const int warpM = wid >> 1;
    const int warpN = wid & 1;

    const int l15 = lane & 15, lq = lane >> 4;
    const int rbl = lq * 8 + (lane & 7);
    const int cob = ((lane >> 3) & 1) * 8;

    const __half* Ag = A + (size_t)bm * DMODEL;
    const __half* Bg = B + (size_t)bn * DMODEL;

    float acc[2][8][4];
#pragma unroll
    for (int i = 0; i < 2; i++)
#pragma unroll
        for (int j = 0; j < 8; j++)
#pragma unroll
            for (int k = 0; k < 4; k++) acc[i][j][k] = 0.f;

    auto load_stage = [&](int chunk, int st) {
        const uint32_t abase = sb + (uint32_t)st * GSTGB;
        const uint32_t bbase = abase + GMATB;
#pragma unroll
        for (int i = 0; i < 4; i++) {
            const int idx = tid + i * 256;     // 0..1023
            const int row = idx >> 3;          // 0..127
            const int c8  = idx & 7;           // 8-half chunk within 64
            const uint32_t so = (uint32_t)(row * GASTR + c8 * 8) * 2u;
            const size_t go = (size_t)row * DMODEL + chunk * GBK + c8 * 8;
            cp_async16(abase + so, Ag + go);
            cp_async16(bbase + so, Bg + go);
        }
    };

    load_stage(0, 0); CP_COMMIT();
    load_stage(1, 1); CP_COMMIT();

    for (int i = 0; i < GNCH; i++) {
        const int st = i % 3;
        if (i == GNCH - 1) { CP_WAIT(0); } else { CP_WAIT(1); }
        __syncthreads();
        if (i + 2 < GNCH) { load_stage(i + 2, (i + 2) % 3); CP_COMMIT(); }

        const uint32_t abase = sb + (uint32_t)st * GSTGB;
        const uint32_t bbase = abase + GMATB;
#pragma unroll
        for (int ks = 0; ks < 4; ks++) {
            uint32_t a[2][4];
#pragma unroll
            for (int mf = 0; mf < 2; mf++)
                ldsm_x4(a[mf][0], a[mf][1], a[mf][2], a[mf][3],
                        abase + (uint32_t)((warpM * 32 + mf * 16 + l15) * GASTR
                                           + ks * 16 + lq * 8) * 2u);
#pragma unroll
            for (int nfp = 0; nfp < 4; nfp++) {
                uint32_t b0, b1, b2, b3;
                ldsm_x4(b0, b1, b2, b3,
                        bbase + (uint32_t)((warpN * 64 + nfp * 16 + rbl) * GASTR
                                           + ks * 16 + cob) * 2u);
#pragma unroll
                for (int mf = 0; mf < 2; mf++) {
                    mma_f16(acc[mf][2 * nfp],     a[mf][0], a[mf][1], a[mf][2], a[mf][3], b0, b1);
                    mma_f16(acc[mf][2 * nfp + 1], a[mf][0], a[mf][1], a[mf][2], a[mf][3], b2, b3);
                }
            }
        }
    }

    // ---------------- epilogue --------------------------------------------
#pragma unroll
    for (int mf = 0; mf < 2; mf++) {
        if (do_rms) {
            float ssl = 0.f, ssh = 0.f;
#pragma unroll
            for (int nf = 0; nf < 8; nf++) {
                ssl += acc[mf][nf][0] * acc[mf][nf][0]
                     + acc[mf][nf][1] * acc[mf][nf][1];
                ssh += acc[mf][nf][2] * acc[mf][nf][2]
                     + acc[mf][nf][3] * acc[mf][nf][3];
            }
            ssl += __shfl_xor_sync(0xFFFFFFFFu, ssl, 1);
            ssl += __shfl_xor_sync(0xFFFFFFFFu, ssl, 2);
            ssh += __shfl_xor_sync(0xFFFFFFFFu, ssh, 1);
            ssh += __shfl_xor_sync(0xFFFFFFFFu, ssh, 2);
            const float rl = rsqrtf(ssl * (1.0f / 64.0f) + F32_EPS);
            const float rh = rsqrtf(ssh * (1.0f / 64.0f) + F32_EPS);
#pragma unroll
            for (int nf = 0; nf < 8; nf++) {
                const int hc = nf * 8 + 2 * t;
                const float w0 = w[hc], w1 = w[hc + 1];
                acc[mf][nf][0] *= rl * w0;
                acc[mf][nf][1] *= rl * w1;
                acc[mf][nf][2] *= rh * w0;
                acc[mf][nf][3] *= rh * w1;
            }
        }
        const int r0 = bm + warpM * 32 + mf * 16 + g;
        const int cc = bn + warpN * 64 + 2 * t;
        if (out_half) {
            __half* C = (__half*)Cv;
            uint32_t* c0 = (uint32_t*)(C + (size_t)r0 * DMODEL + cc);
            uint32_t* c1 = (uint32_t*)(C + (size_t)(r0 + 8) * DMODEL + cc);
#pragma unroll
            for (int nf = 0; nf < 8; nf++) {
                c0[nf * 4] = packh2(acc[mf][nf][0], acc[mf][nf][1]);
                c1[nf * 4] = packh2(acc[mf][nf][2], acc[mf][nf][3]);
            }
        } else {
            float* C = (float*)Cv;
            float* c0 = C + (size_t)r0 * DMODEL + cc;
            float* c1 = C + (size_t)(r0 + 8) * DMODEL + cc;
#pragma unroll
            for (int nf = 0; nf < 8; nf++) {
                *(float2*)(c0 + nf * 8) = make_float2(acc[mf][nf][0], acc[mf][nf][1]);
                *(float2*)(c1 + nf * 8) = make_float2(acc[mf][nf][2], acc[mf][nf][3]);
            }
        }
    }
}

// Fused QKV projection: grid.x = 24 (matrix = x/8, col tile = x%8), grid.y = 64.
__global__ void __launch_bounds__(256)
gemm_qkv(const __half* __restrict__ A,
         const __half* __restrict__ Bqm, const __half* __restrict__ Bkm,
         const __half* __restrict__ Bvm,
         __half* __restrict__ Cq, __half* __restrict__ Ck, __half* __restrict__ Cv_,
         const float* __restrict__ qn, const float* __restrict__ kn)
{
    extern __shared__ __half gsm[];
    const int m = blockIdx.x >> 3;
    const int bn = (blockIdx.x & 7) * 128;
    const __half* B = m == 0 ? Bqm : m == 1 ? Bkm : Bvm;
    __half* C = m == 0 ? Cq : m == 1 ? Ck : Cv_;
    const float* w = m == 0 ? qn : m == 1 ? kn : nullptr;
    gemm_body(gsm, A, B, C, w, m < 2 ? 1 : 0, 1, blockIdx.y * 128, bn);
}

// Single GEMM (output projection), fp32 out.
__global__ void __launch_bounds__(256)
gemm_f16(const __half* __restrict__ A, const __half* __restrict__ B,
         void* __restrict__ Cv, const float* __restrict__ w,
         int do_rms, int out_half)
{
    extern __shared__ __half gsm[];
    gemm_body(gsm, A, B, Cv, w, do_rms, out_half,
              blockIdx.y * 128, blockIdx.x * 128);
}

// ===========================================================================
// fp16 flash attention — no online softmax (|s|<=8 bound), f16x2 exponent,
// 3-buffer KV ring => ONE __syncthreads per tile.
// CTA: 128 q-rows of one (b,h); 8 warps x 16 rows. KV tiles of 64 keys.
// p = ex2.f16x2(s) is directly the PV A-fragment; l = sum of the same fp16 p.
// ===========================================================================
#define HSTR 72                       // halves per smem row (144 B)
#define FA_TILEH (64 * HSTR)          // 4608 halves per KV buffer
#define FA_NT (SEQ / 64)              // 32
#define FA_BYTES (6 * FA_TILEH * 2)   // 55296 B (K0K1K2 V0V1V2)

__global__ void __launch_bounds__(256, 2)
flash_attn_f16(const __half* __restrict__ Q, const __half* __restrict__ K,
               const __half* __restrict__ V, __half* __restrict__ O)
{
    extern __shared__ __half fs[];
    const uint32_t sb = smem_to_u32(fs);
    const int tid  = threadIdx.x;
    const int wid  = tid >> 5;
    const int lane = tid & 31;
    const int g    = lane >> 2;
    const int t    = lane & 3;
    const int bh = blockIdx.y;
    const int b  = bh >> 4;
    const int h  = bh & 15;
    const size_t rowbase = (size_t)b * SEQ;
    const int qm0 = blockIdx.x * 128;
    const int m0  = wid * 16;

    const int l15 = lane & 15, lq = lane >> 4;
    const int rbl = lq * 8 + (lane & 7);             // K ldmatrix row pattern
    const int cob = ((lane >> 3) & 1) * 8;           // K col offset
    const int rv  = ((lane >> 3) & 1) * 8 + (lane & 7);  // V trans row pattern
    const int cv  = lq * 8;                          // V trans col offset

    // ---- stage Q (128 x 64 halves) over K0/K1 region, extract frags ----
    {
        const __half* Qg = Q + (rowbase + qm0) * DMODEL + h * DH;
#pragma unroll
        for (int i = 0; i < 4; i++) {
            const int idx = tid + i * 256;
            const int row = idx >> 3, c8 = idx & 7;
            cp_async16(sb + (uint32_t)(row * HSTR + c8 * 8) * 2u,
                       Qg + (size_t)row * DMODEL + c8 * 8);
        }
        CP_COMMIT(); CP_WAIT(0);
        __syncthreads();
    }
    uint32_t qf[4][4];
    // scale = 1/sqrt(64) * log2(e): ex2(s) == exp(q.k / 8)
    const __half2 qsc = __float2half2_rn(0.125f * 1.4426950408889634f);
#pragma unroll
    for (int ks = 0; ks < 4; ks++) {
        ldsm_x4(qf[ks][0], qf[ks][1], qf[ks][2], qf[ks][3],
                sb + (uint32_t)((m0 + l15) * HSTR + ks * 16 + lq * 8) * 2u);
#pragma unroll
        for (int j = 0; j < 4; j++) {
            __half2* hp = (__half2*)&qf[ks][j];
            *hp = __hmul2(*hp, qsc);
        }
    }
    __syncthreads();   // Q staging region about to be reused by K buffers

    float acc_o[8][4];
#pragma unroll
    for (int j = 0; j < 8; j++)
#pragma unroll
        for (int k = 0; k < 4; k++) acc_o[j][k] = 0.f;
    float lr0 = 0.f, lr1 = 0.f;      // per-thread partial row sums

    auto load_kv = [&](int tile, int buf) {
        const __half* Kg = K + (rowbase + tile * 64) * DMODEL + h * DH;
        const __half* Vg = V + (rowbase + tile * 64) * DMODEL + h * DH;
        const uint32_t kb = sb + (uint32_t)(buf * FA_TILEH) * 2u;
        const uint32_t vb = sb + (uint32_t)((3 + buf) * FA_TILEH) * 2u;
#pragma unroll
        for (int i = 0; i < 2; i++) {
            const int idx = tid + i * 256;
            const int row = idx >> 3, c8 = idx & 7;
            const uint32_t so = (uint32_t)(row * HSTR + c8 * 8) * 2u;
            const size_t go = (size_t)row * DMODEL + c8 * 8;
            cp_async16(kb + so, Kg + go);
            cp_async16(vb + so, Vg + go);
        }
    };

    load_kv(0, 0); CP_COMMIT();
    load_kv(1, 1); CP_COMMIT();

    for (int it = 0; it < FA_NT; it++) {
        const int buf = it % 3;
        if (it + 1 < FA_NT) { CP_WAIT(1); } else { CP_WAIT(0); }
        __syncthreads();     // tile `it` visible; buffer (it-1)%3 free to refill
        if (it + 2 < FA_NT) { load_kv(it + 2, (it + 2) % 3); CP_COMMIT(); }

        // ---- S = Q * K^T (log2 units) ----
        float s[8][4];
#pragma unroll
        for (int j = 0; j < 8; j++)
#pragma unroll
            for (int k = 0; k < 4; k++) s[j][k] = 0.f;

        const uint32_t kbase = sb + (uint32_t)(buf * FA_TILEH) * 2u;
#pragma unroll
        for (int ks = 0; ks < 4; ks++) {
#pragma unroll
            for (int nfp = 0; nfp < 4; nfp++) {
                uint32_t b0, b1, b2, b3;
                ldsm_x4(b0, b1, b2, b3,
                        kbase + (uint32_t)((nfp * 16 + rbl) * HSTR
                                           + ks * 16 + cob) * 2u);
                mma_f16(s[2 * nfp],     qf[ks][0], qf[ks][1], qf[ks][2], qf[ks][3], b0, b1);
                mma_f16(s[2 * nfp + 1], qf[ks][0], qf[ks][1], qf[ks][2], qf[ks][3], b2, b3);
            }
        }

        // ---- p = 2^s via f16x2 MUFU; half2 row-sum trees; p IS the A-frag ----
        uint32_t ph[8][2];
        __half2 sum0 = __float2half2_rn(0.f);
        __half2 sum1 = __float2half2_rn(0.f);
#pragma unroll
        for (int nf = 0; nf < 8; nf++) {
            ph[nf][0] = h2ex2(packh2(s[nf][0], s[nf][1]));
            ph[nf][1] = h2ex2(packh2(s[nf][2], s[nf][3]));
            sum0 = __hadd2(sum0, *(__half2*)&ph[nf][0]);
            sum1 = __hadd2(sum1, *(__half2*)&ph[nf][1]);
        }
        {
            float2 f0 = __half22float2(sum0);
            float2 f1 = __half22float2(sum1);
            lr0 += f0.x + f0.y;
            lr1 += f1.x + f1.y;
        }

        // ---- O += P * V ----
        const uint32_t vbase = sb + (uint32_t)((3 + buf) * FA_TILEH) * 2u;
#pragma unroll
        for (int ks = 0; ks < 4; ks++) {
#pragma unroll
            for (int nfp = 0; nfp < 4; nfp++) {
                uint32_t b0, b1, b2, b3;
                ldsm_x4_t(b0, b1, b2, b3,
                          vbase + (uint32_t)((ks * 16 + rv) * HSTR
                                             + nfp * 16 + cv) * 2u);
                mma_f16(acc_o[2 * nfp],     ph[2 * ks][0], ph[2 * ks][1],
                        ph[2 * ks + 1][0], ph[2 * ks + 1][1], b0, b1);
                mma_f16(acc_o[2 * nfp + 1], ph[2 * ks][0], ph[2 * ks][1],
                        ph[2 * ks + 1][0], ph[2 * ks + 1][1], b2, b3);
            }
        }
    }

    // ---- epilogue: reduce l across quad once, O / l -> fp16 global ----
    lr0 += __shfl_xor_sync(0xFFFFFFFFu, lr0, 1);
    lr0 += __shfl_xor_sync(0xFFFFFFFFu, lr0, 2);
    lr1 += __shfl_xor_sync(0xFFFFFFFFu, lr1, 1);
    lr1 += __shfl_xor_sync(0xFFFFFFFFu, lr1, 2);
    const float inv0 = 1.f / lr0;
    const float inv1 = 1.f / lr1;
    __half* o0 = O + (rowbase + qm0 + m0 + g) * (size_t)DMODEL + h * DH + 2 * t;
    __half* o1 = o0 + 8 * DMODEL;
#pragma unroll
    for (int nf = 0; nf < 8; nf++) {
        *(uint32_t*)(o0 + nf * 8) = packh2(acc_o[nf][0] * inv0, acc_o[nf][1] * inv0);
        *(uint32_t*)(o1 + nf * 8) = packh2(acc_o[nf][2] * inv1, acc_o[nf][3] * inv1);
    }
}

// ---------------------------------------------------------------------------
// Launch.
// ---------------------------------------------------------------------------
extern "C" void kernel_launch(void* const* d_in, const int* in_sizes, int n_in,
                              void* d_out, int out_size)
{
    const float* x  = (const float*)d_in[0];
    const float* Wq = (const float*)d_in[1];
    const float* Wk = (const float*)d_in[2];
    const float* Wv = (const float*)d_in[3];
    const float* Wo = (const float*)d_in[4];
    const float* qn = (const float*)d_in[5];
    const float* kn = (const float*)d_in[6];
    float* out = (float*)d_out;

    __half *xh, *wqh, *wkh, *wvh, *woh, *Qh, *Kh, *Vh, *Oh;
    cudaGetSymbolAddress((void**)&xh,  g_xh);
    cudaGetSymbolAddress((void**)&wqh, g_Wqh);
    cudaGetSymbolAddress((void**)&wkh, g_Wkh);
    cudaGetSymbolAddress((void**)&wvh, g_Wvh);
    cudaGetSymbolAddress((void**)&woh, g_Woh);
    cudaGetSymbolAddress((void**)&Qh,  g_Qh);
    cudaGetSymbolAddress((void**)&Kh,  g_Kh);
    cudaGetSymbolAddress((void**)&Vh,  g_Vh);
    cudaGetSymbolAddress((void**)&Oh,  g_Oh);

    cudaFuncSetAttribute(gemm_f16,
                         cudaFuncAttributeMaxDynamicSharedMemorySize, GSM_BYTES);
    cudaFuncSetAttribute(gemm_qkv,
                         cudaFuncAttributeMaxDynamicSharedMemorySize, GSM_BYTES);
    cudaFuncSetAttribute(flash_attn_f16,
                         cudaFuncAttributeMaxDynamicSharedMemorySize, FA_BYTES);

    // fused fp32 -> fp16 conversion (x + 4 weights)
    const int ntot = NX4 + 4 * NW4;             // 3145728
    cvt_all<<<ntot / 256, 256>>>((const float4*)x, (const float4*)Wq,
                                 (const float4*)Wk, (const float4*)Wv,
                                 (const float4*)Wo,
                                 (uint2*)xh, (uint2*)wqh, (uint2*)wkh,
                                 (uint2*)wvh, (uint2*)woh);

    // fused QKV projection
    gemm_qkv<<<dim3(24, ROWS / 128), 256, GSM_BYTES>>>(
        xh, wqh, wkh, wvh, Qh, Kh, Vh, qn, kn);

    flash_attn_f16<<<dim3(SEQ / 128, Bq * NH), 256, FA_BYTES>>>(Qh, Kh, Vh, Oh);

    gemm_f16<<<dim3(DMODEL / 128, ROWS / 128), 256, GSM_BYTES>>>(
        Oh, woh, out, nullptr, 0, 0);
}

// round 8
// speedup vs baseline: 12.8359x; 1.0281x over previous
#include <cuda_runtime.h>
#include <cuda_fp16.h>
#include <math.h>
#include <cstdint>

// Problem shape (fixed by the reference).
#define Bq      4
#define SEQ     2048
#define DMODEL  1024
#define NH      16
#define DH      64
#define ROWS    (Bq * SEQ)      // 8192

#define F32_EPS 1.1920929e-07f

// fp16 scratch: device globals (no cudaMalloc allowed).
__device__ __half g_xh[ROWS * DMODEL];
__device__ __half g_Wqh[DMODEL * DMODEL];
__device__ __half g_Wkh[DMODEL * DMODEL];
__device__ __half g_Wvh[DMODEL * DMODEL];
__device__ __half g_Woh[DMODEL * DMODEL];
__device__ __half g_Qh[ROWS * DMODEL];
__device__ __half g_Kh[ROWS * DMODEL];
__device__ __half g_Vh[ROWS * DMODEL];
__device__ __half g_Oh[ROWS * DMODEL];

// ===========================================================================
// Helpers.
// ===========================================================================
__device__ __forceinline__ uint32_t smem_to_u32(const void* p) {
    uint32_t a;
    asm("{ .reg .u64 t; cvta.to.shared.u64 t, %1; cvt.u32.u64 %0, t; }"
        : "=r"(a) : "l"(p));
    return a;
}
__device__ __forceinline__ void mma_f16(float* c, uint32_t a0, uint32_t a1,
                                        uint32_t a2, uint32_t a3,
                                        uint32_t b0, uint32_t b1) {
    asm volatile(
        "mma.sync.aligned.m16n8k16.row.col.f32.f16.f16.f32 "
        "{%0,%1,%2,%3}, {%4,%5,%6,%7}, {%8,%9}, {%0,%1,%2,%3};"
        : "+f"(c[0]), "+f"(c[1]), "+f"(c[2]), "+f"(c[3])
        : "r"(a0), "r"(a1), "r"(a2), "r"(a3), "r"(b0), "r"(b1));
}
__device__ __forceinline__ void ldsm_x4(uint32_t& r0, uint32_t& r1,
                                        uint32_t& r2, uint32_t& r3, uint32_t a) {
    asm volatile("ldmatrix.sync.aligned.m8n8.x4.shared.b16 {%0,%1,%2,%3}, [%4];"
                 : "=r"(r0), "=r"(r1), "=r"(r2), "=r"(r3) : "r"(a));
}
__device__ __forceinline__ void ldsm_x4_t(uint32_t& r0, uint32_t& r1,
                                          uint32_t& r2, uint32_t& r3, uint32_t a) {
    asm volatile("ldmatrix.sync.aligned.m8n8.x4.trans.shared.b16 {%0,%1,%2,%3}, [%4];"
                 : "=r"(r0), "=r"(r1), "=r"(r2), "=r"(r3) : "r"(a));
}
__device__ __forceinline__ void cp_async16(uint32_t dst, const void* src) {
    asm volatile("cp.async.cg.shared.global [%0], [%1], 16;"
                 :: "r"(dst), "l"(src));
}
#define CP_COMMIT() asm volatile("cp.async.commit_group;" ::: "memory")
#define CP_WAIT(n)  asm volatile("cp.async.wait_group %0;" :: "n"(n) : "memory")

__device__ __forceinline__ uint32_t packh2(float x, float y) {
    __half2 h = __floats2half2_rn(x, y);
    return *(uint32_t*)&h;
}
// 2 exponentials (base 2) on a packed half2 in ONE MUFU op.
__device__ __forceinline__ uint32_t h2ex2(uint32_t x) {
    uint32_t r;
    asm("ex2.approx.f16x2 %0, %1;" : "=r"(r) : "r"(x));
    return r;
}

// ===========================================================================
// Fused fp32 -> fp16 conversion: x (2M float4) then 4 weights (256K each).
// ===========================================================================
#define NX4 (ROWS * DMODEL / 4)      // 2097152
#define NW4 (DMODEL * DMODEL / 4)    // 262144

__global__ void cvt_all(const float4* __restrict__ x,
                        const float4* __restrict__ w0,
                        const float4* __restrict__ w1,
                        const float4* __restrict__ w2,
                        const float4* __restrict__ w3,
                        uint2* __restrict__ dx, uint2* __restrict__ dw0,
                        uint2* __restrict__ dw1, uint2* __restrict__ dw2,
                        uint2* __restrict__ dw3)
{
    int i = blockIdx.x * blockDim.x + threadIdx.x;
    const float4* s;
    uint2* d;
    int idx;
    if (i < NX4) {
        s = x; d = dx; idx = i;
    } else {
        int j = i - NX4;
        int wsel = j >> 18;                 // NW4 = 2^18
        idx = j & (NW4 - 1);
        s = wsel == 0 ? w0 : wsel == 1 ? w1 : wsel == 2 ? w2 : w3;
        d = wsel == 0 ? dw0 : wsel == 1 ? dw1 : wsel == 2 ? dw2 : dw3;
    }
    float4 v = s[idx];
    d[idx] = make_uint2(packh2(v.x, v.y), packh2(v.z, v.w));
}

// ===========================================================================
// fp16 tensor-core GEMM body (NT): C[M,N] = A[M,K]*B[N,K]^T, fp32 accum.
// CTA 128x128, BK=64, 3-stage cp.async pipeline, 128 threads:
// 4 warps (2M x 2N), warp tile 64x64 = 4 mf x 8 nf of m16n8k16.
// MMA:LDSM ratio 4:1 (each fragment reused across 4 m-frags / 8 n-frags).
// ===========================================================================
#define GBK     64
#define GNCH    (DMODEL / GBK)       // 16
#define GASTR   72                   // halves per smem row (144 B)
#define GMATB   (128 * GASTR * 2)    // 18432 bytes per matrix per stage
#define GSTGB   (2 * GMATB)          // 36864 bytes per stage
#define GSM_BYTES (3 * GSTGB)        // 110592

__device__ __forceinline__ void
gemm_body(__half* gsm, const __half* __restrict__ A, const __half* __restrict__ B,
          void* __restrict__ Cv, const float* __restrict__ w,
          int do_rms, int out_half, int bm, int bn)
{
    const uint32_t sb = smem_to_u32(gsm);
    const int tid  = threadIdx.x;
    const int wid  = tid >> 5;
    const int lane = tid & 31;
    const int g    = lane >> 2;
    const int t    = lane & 3;
    const int warpM = wid >> 1;       // 0..1, 64 rows each
    const int warpN = wid & 1;        // 0..1, 64 cols each

    const int l15 = lane & 15, lq = lane >> 4;
    const int rbl = lq * 8 + (lane & 7);
    const int cob = ((lane >> 3) & 1) * 8;

    const __half* Ag = A + (size_t)bm * DMODEL;
    const __half* Bg = B + (size_t)bn * DMODEL;

    float acc[4][8][4];
#pragma unroll
    for (int i = 0; i < 4; i++)
#pragma unroll
        for (int j = 0; j < 8; j++)
#pragma unroll
            for (int k = 0; k < 4; k++) acc[i][j][k] = 0.f;

    auto load_stage = [&](int chunk, int st) {
        const uint32_t abase = sb + (uint32_t)st * GSTGB;
        const uint32_t bbase = abase + GMATB;
#pragma unroll
        for (int i = 0; i < 8; i++) {
            const int idx = tid + i * 128;     // 0..1023
            const int row = idx >> 3;          // 0..127
            const int c8  = idx & 7;           // 8-half chunk within 64
            const uint32_t so = (uint32_t)(row * GASTR + c8 * 8) * 2u;
            const size_t go = (size_t)row * DMODEL + chunk * GBK + c8 * 8;
            cp_async16(abase + so, Ag + go);
            cp_async16(bbase + so, Bg + go);
        }
    };

    load_stage(0, 0); CP_COMMIT();
    load_stage(1, 1); CP_COMMIT();

    for (int i = 0; i < GNCH; i++) {
        const int st = i % 3;
        if (i == GNCH - 1) { CP_WAIT(0); } else { CP_WAIT(1); }
        __syncthreads();
        if (i + 2 < GNCH) { load_stage(i + 2, (i + 2) % 3); CP_COMMIT(); }

        const uint32_t abase = sb + (uint32_t)st * GSTGB;
        const uint32_t bbase = abase + GMATB;
#pragma unroll
        for (int ks = 0; ks < 4; ks++) {
            uint32_t a[4][4];
#pragma unroll
            for (int mf = 0; mf < 4; mf++)
                ldsm_x4(a[mf][0], a[mf][1], a[mf][2], a[mf][3],
                        abase + (uint32_t)((warpM * 64 + mf * 16 + l15) * GASTR
                                           + ks * 16 + lq * 8) * 2u);
#pragma unroll
            for (int nfp = 0; nfp < 4; nfp++) {
                uint32_t b0, b1, b2, b3;
                ldsm_x4(b0, b1, b2, b3,
                        bbase + (uint32_t)((warpN * 64 + nfp * 16 + rbl) * GASTR
                                           + ks * 16 + cob) * 2u);
#pragma unroll
                for (int mf = 0; mf < 4; mf++) {
                    mma_f16(acc[mf][2 * nfp],     a[mf][0], a[mf][1], a[mf][2], a[mf][3], b0, b1);
                    mma_f16(acc[mf][2 * nfp + 1], a[mf][0], a[mf][1], a[mf][2], a[mf][3], b2, b3);
                }
            }
        }
    }

    // ---------------- epilogue --------------------------------------------
#pragma unroll
    for (int mf = 0; mf < 4; mf++) {
        if (do_rms) {
            float ssl = 0.f, ssh = 0.f;
#pragma unroll
            for (int nf = 0; nf < 8; nf++) {
                ssl += acc[mf][nf][0] * acc[mf][nf][0]
                     + acc[mf][nf][1] * acc[mf][nf][1];
                ssh += acc[mf][nf][2] * acc[mf][nf][2]
                     + acc[mf][nf][3] * acc[mf][nf][3];
            }
            ssl += __shfl_xor_sync(0xFFFFFFFFu, ssl, 1);
            ssl += __shfl_xor_sync(0xFFFFFFFFu, ssl, 2);
            ssh += __shfl_xor_sync(0xFFFFFFFFu, ssh, 1);
            ssh += __shfl_xor_sync(0xFFFFFFFFu, ssh, 2);
            const float rl = rsqrtf(ssl * (1.0f / 64.0f) + F32_EPS);
            const float rh = rsqrtf(ssh * (1.0f / 64.0f) + F32_EPS);
#pragma unroll
            for (int nf = 0; nf < 8; nf++) {
                const int hc = nf * 8 + 2 * t;
                const float w0 = w[hc], w1 = w[hc + 1];
                acc[mf][nf][0] *= rl * w0;
                acc[mf][nf][1] *= rl * w1;
                acc[mf][nf][2] *= rh * w0;
                acc[mf][nf][3] *= rh * w1;
            }
        }
        const int r0 = bm + warpM * 64 + mf * 16 + g;
        const int cc = bn + warpN * 64 + 2 * t;
        if (out_half) {
            __half* C = (__half*)Cv;
            uint32_t* c0 = (uint32_t*)(C + (size_t)r0 * DMODEL + cc);
            uint32_t* c1 = (uint32_t*)(C + (size_t)(r0 + 8) * DMODEL + cc);
#pragma unroll
            for (int nf = 0; nf < 8; nf++) {
                c0[nf * 4] = packh2(acc[mf][nf][0], acc[mf][nf][1]);
                c1[nf * 4] = packh2(acc[mf][nf][2], acc[mf][nf][3]);
            }
        } else {
            float* C = (float*)Cv;
            float* c0 = C + (size_t)r0 * DMODEL + cc;
            float* c1 = C + (size_t)(r0 + 8) * DMODEL + cc;
#pragma unroll
            for (int nf = 0; nf < 8; nf++) {
                *(float2*)(c0 + nf * 8) = make_float2(acc[mf][nf][0], acc[mf][nf][1]);
                *(float2*)(c1 + nf * 8) = make_float2(acc[mf][nf][2], acc[mf][nf][3]);
            }
        }
    }
}

// Fused QKV projection: grid.x = 24 (matrix = x/8, col tile = x%8), grid.y = 64.
__global__ void __launch_bounds__(128, 2)
gemm_qkv(const __half* __restrict__ A,
         const __half* __restrict__ Bqm, const __half* __restrict__ Bkm,
         const __half* __restrict__ Bvm,
         __half* __restrict__ Cq, __half* __restrict__ Ck, __half* __restrict__ Cv_,
         const float* __restrict__ qn, const float* __restrict__ kn)
{
    extern __shared__ __half gsm[];
    const int m = blockIdx.x >> 3;
    const int bn = (blockIdx.x & 7) * 128;
    const __half* B = m == 0 ? Bqm : m == 1 ? Bkm : Bvm;
    __half* C = m == 0 ? Cq : m == 1 ? Ck : Cv_;
    const float* w = m == 0 ? qn : m == 1 ? kn : nullptr;
    gemm_body(gsm, A, B, C, w, m < 2 ? 1 : 0, 1, blockIdx.y * 128, bn);
}

// Single GEMM (output projection), fp32 out.
__global__ void __launch_bounds__(128, 2)
gemm_f16(const __half* __restrict__ A, const __half* __restrict__ B,
         void* __restrict__ Cv, const float* __restrict__ w,
         int do_rms, int out_half)
{
    extern __shared__ __half gsm[];
    gemm_body(gsm, A, B, Cv, w, do_rms, out_half,
              blockIdx.y * 128, blockIdx.x * 128);
}

// ===========================================================================
// fp16 flash attention — no online softmax (|s|<=8 bound), f16x2 exponent,
// 3-buffer KV ring (one __syncthreads per tile).
// 128 threads: 4 warps x 32 q-rows (2 m-frags each); CTA = 128 q-rows.
// Each K/V fragment is loaded once per warp and reused across 2 m-frags.
// ===========================================================================
#define HSTR 72                       // halves per smem row (144 B)
#define FA_TILEH (64 * HSTR)          // 4608 halves per KV buffer
#define FA_NT (SEQ / 64)              // 32
#define FA_BYTES (6 * FA_TILEH * 2)   // 55296 B (K0K1K2 V0V1V2)

__global__ void __launch_bounds__(128, 2)
flash_attn_f16(const __half* __restrict__ Q, const __half* __restrict__ K,
               const __half* __restrict__ V, __half* __restrict__ O)
{
    extern __shared__ __half fs[];
    const uint32_t sb = smem_to_u32(fs);
    const int tid  = threadIdx.x;
    const int wid  = tid >> 5;
    const int lane = tid & 31;
    const int g    = lane >> 2;
    const int t    = lane & 3;
    const int bh = blockIdx.y;
    const int b  = bh >> 4;
    const int h  = bh & 15;
    const size_t rowbase = (size_t)b * SEQ;
    const int qm0 = blockIdx.x * 128;
    const int m0  = wid * 32;

    const int l15 = lane & 15, lq = lane >> 4;
    const int rbl = lq * 8 + (lane & 7);             // K ldmatrix row pattern
    const int cob = ((lane >> 3) & 1) * 8;           // K col offset
    const int rv  = ((lane >> 3) & 1) * 8 + (lane & 7);  // V trans row pattern
    const int cv  = lq * 8;                          // V trans col offset

    // ---- stage Q (128 x 64 halves) over K0/K1 region, extract frags ----
    {
        const __half* Qg = Q + (rowbase + qm0) * DMODEL + h * DH;
#pragma unroll
        for (int i = 0; i < 8; i++) {
            const int idx = tid + i * 128;
            const int row = idx >> 3, c8 = idx & 7;
            cp_async16(sb + (uint32_t)(row * HSTR + c8 * 8) * 2u,
                       Qg + (size_t)row * DMODEL + c8 * 8);
        }
        CP_COMMIT(); CP_WAIT(0);
        __syncthreads();
    }
    uint32_t qf[2][4][4];
    // scale = 1/sqrt(64) * log2(e): ex2(s) == exp(q.k / 8)
    const __half2 qsc = __float2half2_rn(0.125f * 1.4426950408889634f);
#pragma unroll
    for (int mf = 0; mf < 2; mf++)
#pragma unroll
        for (int ks = 0; ks < 4; ks++) {
            ldsm_x4(qf[mf][ks][0], qf[mf][ks][1], qf[mf][ks][2], qf[mf][ks][3],
                    sb + (uint32_t)((m0 + mf * 16 + l15) * HSTR
                                    + ks * 16 + lq * 8) * 2u);
#pragma unroll
            for (int j = 0; j < 4; j++) {
                __half2* hp = (__half2*)&qf[mf][ks][j];
                *hp = __hmul2(*hp, qsc);
            }
        }
    __syncthreads();   // Q staging region about to be reused by K buffers

    float acc_o[2][8][4];
#pragma unroll
    for (int i = 0; i < 2; i++)
#pragma unroll
        for (int j = 0; j < 8; j++)
#pragma unroll
            for (int k = 0; k < 4; k++) acc_o[i][j][k] = 0.f;
    float lr[2][2] = {{0.f, 0.f}, {0.f, 0.f}};

    auto load_kv = [&](int tile, int buf) {
        const __half* Kg = K + (rowbase + tile * 64) * DMODEL + h * DH;
        const __half* Vg = V + (rowbase + tile * 64) * DMODEL + h * DH;
        const uint32_t kb = sb + (uint32_t)(buf * FA_TILEH) * 2u;
        const uint32_t vb = sb + (uint32_t)((3 + buf) * FA_TILEH) * 2u;
#pragma unroll
        for (int i = 0; i < 4; i++) {
            const int idx = tid + i * 128;
            const int row = idx >> 3, c8 = idx & 7;
            const uint32_t so = (uint32_t)(row * HSTR + c8 * 8) * 2u;
            const size_t go = (size_t)row * DMODEL + c8 * 8;
            cp_async16(kb + so, Kg + go);
            cp_async16(vb + so, Vg + go);
        }
    };

    load_kv(0, 0); CP_COMMIT();
    load_kv(1, 1); CP_COMMIT();

    for (int it = 0; it < FA_NT; it++) {
        const int buf = it % 3;
        if (it + 1 < FA_NT) { CP_WAIT(1); } else { CP_WAIT(0); }
        __syncthreads();     // tile `it` visible; buffer (it-1)%3 free to refill
        if (it + 2 < FA_NT) { load_kv(it + 2, (it + 2) % 3); CP_COMMIT(); }

        // ---- S = Q * K^T (log2 units) ----
        float s[2][8][4];
#pragma unroll
        for (int i = 0; i < 2; i++)
#pragma unroll
            for (int j = 0; j < 8; j++)
#pragma unroll
                for (int k = 0; k < 4; k++) s[i][j][k] = 0.f;

        const uint32_t kbase = sb + (uint32_t)(buf * FA_TILEH) * 2u;
#pragma unroll
        for (int ks = 0; ks < 4; ks++) {
#pragma unroll
            for (int nfp = 0; nfp < 4; nfp++) {
                uint32_t b0, b1, b2, b3;
                ldsm_x4(b0, b1, b2, b3,
                        kbase + (uint32_t)((nfp * 16 + rbl) * HSTR
                                           + ks * 16 + cob) * 2u);
#pragma unroll
                for (int mf = 0; mf < 2; mf++) {
                    mma_f16(s[mf][2 * nfp],     qf[mf][ks][0], qf[mf][ks][1],
                            qf[mf][ks][2], qf[mf][ks][3], b0, b1);
                    mma_f16(s[mf][2 * nfp + 1], qf[mf][ks][0], qf[mf][ks][1],
                            qf[mf][ks][2], qf[mf][ks][3], b2, b3);
                }
            }
        }

        // ---- p = 2^s via f16x2 MUFU; half2 row-sum trees; p IS the A-frag ----
        uint32_t ph[2][8][2];
#pragma unroll
        for (int mf = 0; mf < 2; mf++) {
            __half2 sum0 = __float2half2_rn(0.f);
            __half2 sum1 = __float2half2_rn(0.f);
#pragma unroll
            for (int nf = 0; nf < 8; nf++) {
                ph[mf][nf][0] = h2ex2(packh2(s[mf][nf][0], s[mf][nf][1]));
                ph[mf][nf][1] = h2ex2(packh2(s[mf][nf][2], s[mf][nf][3]));
                sum0 = __hadd2(sum0, *(__half2*)&ph[mf][nf][0]);
                sum1 = __hadd2(sum1, *(__half2*)&ph[mf][nf][1]);
            }
            float2 f0 = __half22float2(sum0);
            float2 f1 = __half22float2(sum1);
            lr[mf][0] += f0.x + f0.y;
            lr[mf][1] += f1.x + f1.y;
        }

        // ---- O += P * V ----
        const uint32_t vbase = sb + (uint32_t)((3 + buf) * FA_TILEH) * 2u;
#pragma unroll
        for (int ks = 0; ks < 4; ks++) {
#pragma unroll
            for (int nfp = 0; nfp < 4; nfp++) {
                uint32_t b0, b1, b2, b3;
                ldsm_x4_t(b0, b1, b2, b3,
                          vbase + (uint32_t)((ks * 16 + rv) * HSTR
                                             + nfp * 16 + cv) * 2u);
#pragma unroll
                for (int mf = 0; mf < 2; mf++) {
                    mma_f16(acc_o[mf][2 * nfp],     ph[mf][2 * ks][0], ph[mf][2 * ks][1],
                            ph[mf][2 * ks + 1][0], ph[mf][2 * ks + 1][1], b0, b1);
                    mma_f16(acc_o[mf][2 * nfp + 1], ph[mf][2 * ks][0], ph[mf][2 * ks][1],
                            ph[mf][2 * ks + 1][0], ph[mf][2 * ks + 1][1], b2, b3);
                }
            }
        }
    }

    // ---- epilogue: reduce l across quad once, O / l -> fp16 global ----
#pragma unroll
    for (int mf = 0; mf < 2; mf++) {
        float l0 = lr[mf][0], l1 = lr[mf][1];
        l0 += __shfl_xor_sync(0xFFFFFFFFu, l0, 1);
        l0 += __shfl_xor_sync(0xFFFFFFFFu, l0, 2);
        l1 += __shfl_xor_sync(0xFFFFFFFFu, l1, 1);
        l1 += __shfl_xor_sync(0xFFFFFFFFu, l1, 2);
        const float inv0 = 1.f / l0;
        const float inv1 = 1.f / l1;
        __half* o0 = O + (rowbase + qm0 + m0 + mf * 16 + g) * (size_t)DMODEL
                       + h * DH + 2 * t;
        __half* o1 = o0 + 8 * DMODEL;
#pragma unroll
        for (int nf = 0; nf < 8; nf++) {
            *(uint32_t*)(o0 + nf * 8) =
                packh2(acc_o[mf][nf][0] * inv0, acc_o[mf][nf][1] * inv0);
            *(uint32_t*)(o1 + nf * 8) =
                packh2(acc_o[mf][nf][2] * inv1, acc_o[mf][nf][3] * inv1);
        }
    }
}

// ---------------------------------------------------------------------------
// Launch.
// ---------------------------------------------------------------------------
extern "C" void kernel_launch(void* const* d_in, const int* in_sizes, int n_in,
                              void* d_out, int out_size)
{
    const float* x  = (const float*)d_in[0];
    const float* Wq = (const float*)d_in[1];
    const float* Wk = (const float*)d_in[2];
    const float* Wv = (const float*)d_in[3];
    const float* Wo = (const float*)d_in[4];
    const float* qn = (const float*)d_in[5];
    const float* kn = (const float*)d_in[6];
    float* out = (float*)d_out;

    __half *xh, *wqh, *wkh, *wvh, *woh, *Qh, *Kh, *Vh, *Oh;
    cudaGetSymbolAddress((void**)&xh,  g_xh);
    cudaGetSymbolAddress((void**)&wqh, g_Wqh);
    cudaGetSymbolAddress((void**)&wkh, g_Wkh);
    cudaGetSymbolAddress((void**)&wvh, g_Wvh);
    cudaGetSymbolAddress((void**)&woh, g_Woh);
    cudaGetSymbolAddress((void**)&Qh,  g_Qh);
    cudaGetSymbolAddress((void**)&Kh,  g_Kh);
    cudaGetSymbolAddress((void**)&Vh,  g_Vh);
    cudaGetSymbolAddress((void**)&Oh,  g_Oh);

    cudaFuncSetAttribute(gemm_f16,
                         cudaFuncAttributeMaxDynamicSharedMemorySize, GSM_BYTES);
    cudaFuncSetAttribute(gemm_qkv,
                         cudaFuncAttributeMaxDynamicSharedMemorySize, GSM_BYTES);
    cudaFuncSetAttribute(flash_attn_f16,
                         cudaFuncAttributeMaxDynamicSharedMemorySize, FA_BYTES);

    // fused fp32 -> fp16 conversion (x + 4 weights)
    const int ntot = NX4 + 4 * NW4;             // 3145728
    cvt_all<<<ntot / 256, 256>>>((const float4*)x, (const float4*)Wq,
                                 (const float4*)Wk, (const float4*)Wv,
                                 (const float4*)Wo,
                                 (uint2*)xh, (uint2*)wqh, (uint2*)wkh,
                                 (uint2*)wvh, (uint2*)woh);

    // fused QKV projection
    gemm_qkv<<<dim3(24, ROWS / 128), 128, GSM_BYTES>>>(
        xh, wqh, wkh, wvh, Qh, Kh, Vh, qn, kn);

    flash_attn_f16<<<dim3(SEQ / 128, Bq * NH), 128, FA_BYTES>>>(Qh, Kh, Vh, Oh);

    gemm_f16<<<dim3(DMODEL / 128, ROWS / 128), 128, GSM_BYTES>>>(
        Oh, woh, out, nullptr, 0, 0);
}